// round 1
// baseline (speedup 1.0000x reference)
#include <cuda_runtime.h>
#include <math.h>
#include <stdint.h>

#define N_NODES 4096
#define N_EDGES 16384
#define D_IN    128
#define HID     1024

// ---------------- scratch (device globals; no allocation allowed) ----------
__device__ float g_eH[N_NODES * D_IN];
__device__ float g_Ho[N_NODES * D_IN];
__device__ float g_Hi[N_NODES * D_IN];
__device__ int   g_src[N_EDGES];
__device__ int   g_dst[N_EDGES];
__device__ float g_x [N_NODES * 3 * D_IN];
__device__ float g_h1[N_NODES * HID];
__device__ float g_h2[N_NODES * HID];
__device__ float g_h3[N_NODES * (HID / 2)];
__device__ float g_h4[N_NODES * (HID / 4)];

// ---------------- kernel 1: eH = e*H, zero Ho/Hi ---------------------------
__global__ void k_prep(const float* __restrict__ H, const float* __restrict__ e) {
    int idx = blockIdx.x * blockDim.x + threadIdx.x;          // float4 index
    const int total4 = N_NODES * D_IN / 4;                    // 131072
    if (idx >= total4) return;
    int node = idx / (D_IN / 4);
    float ev = e[node];
    float4 h = ((const float4*)H)[idx];
    float4 r = make_float4(ev * h.x, ev * h.y, ev * h.z, ev * h.w);
    ((float4*)g_eH)[idx] = r;
    float4 z = make_float4(0.f, 0.f, 0.f, 0.f);
    ((float4*)g_Ho)[idx] = z;
    ((float4*)g_Hi)[idx] = z;
}

// ---------------- kernel 2: recover indices from one-hot rows --------------
// grid (N_EDGES, 2), 128 threads; each block scans one 4096-float row.
__global__ void k_extract(const float* __restrict__ Ro, const float* __restrict__ Ri) {
    int e = blockIdx.x;
    const float* row = (blockIdx.y == 0 ? Ro : Ri) + (size_t)e * N_NODES;
    int* out = (blockIdx.y == 0 ? g_src : g_dst);
    int t = threadIdx.x;
    #pragma unroll
    for (int i = 0; i < 8; i++) {
        int v4 = t + i * 128;                                  // float4 index, 0..1023
        float4 v = ((const float4*)row)[v4];
        if (v.x != 0.f || v.y != 0.f || v.z != 0.f || v.w != 0.f) {
            int base = v4 * 4;
            int col = (v.x != 0.f) ? base : (v.y != 0.f) ? base + 1
                    : (v.z != 0.f) ? base + 2 : base + 3;
            out[e] = col;
        }
    }
}

// ---------------- kernel 3: edge scatter ------------------------------------
// one warp per edge; lane l handles float4 chunk l (D_IN=128 -> 32 float4).
__global__ void k_scatter() {
    int gtid = blockIdx.x * blockDim.x + threadIdx.x;
    int warp = gtid >> 5;
    int lane = gtid & 31;
    if (warp >= N_EDGES) return;
    int s = g_src[warp];
    int d = g_dst[warp];
    float4 vs = ((const float4*)(g_eH + (size_t)s * D_IN))[lane];
    float4 vd = ((const float4*)(g_eH + (size_t)d * D_IN))[lane];
    float* ho = g_Ho + (size_t)d * D_IN + lane * 4;  // Ho[dst] += eH[src]
    float* hi = g_Hi + (size_t)s * D_IN + lane * 4;  // Hi[src] += eH[dst]
    atomicAdd(ho + 0, vs.x); atomicAdd(ho + 1, vs.y);
    atomicAdd(ho + 2, vs.z); atomicAdd(ho + 3, vs.w);
    atomicAdd(hi + 0, vd.x); atomicAdd(hi + 1, vd.y);
    atomicAdd(hi + 2, vd.z); atomicAdd(hi + 3, vd.w);
}

// ---------------- kernel 4: x = concat(Ho, H, Hi) ---------------------------
__global__ void k_concat(const float* __restrict__ H) {
    int idx = blockIdx.x * blockDim.x + threadIdx.x;           // float4 index
    const int per_row4 = 3 * D_IN / 4;                         // 96
    const int total4 = N_NODES * per_row4;
    if (idx >= total4) return;
    int node = idx / per_row4;
    int c4 = idx - node * per_row4;                            // 0..95
    float4 v;
    if (c4 < 32)       v = ((const float4*)(g_Ho + (size_t)node * D_IN))[c4];
    else if (c4 < 64)  v = ((const float4*)(H    + (size_t)node * D_IN))[c4 - 32];
    else               v = ((const float4*)(g_Hi + (size_t)node * D_IN))[c4 - 64];
    ((float4*)g_x)[idx] = v;
}

// ---------------- fused SGEMM + bias + tanh ---------------------------------
// C[M,N] = tanh(A[M,K] @ W[K,N] + bias[N]); BM=BN=128, BK=16, 256 thr, 8x8/thr
__global__ __launch_bounds__(256, 2)
void k_gemm_tanh(const float* __restrict__ A, const float* __restrict__ W,
                 const float* __restrict__ bias, float* __restrict__ C,
                 int M, int N, int K) {
    __shared__ float As[16][128];
    __shared__ float Bs[16][128];
    const int tid = threadIdx.x;
    const int bm0 = blockIdx.y * 128;
    const int bn0 = blockIdx.x * 128;
    const int tm = (tid / 16) * 8;
    const int tn = (tid % 16) * 8;

    const int arow = tid / 4;          // 0..63
    const int acol = (tid % 4) * 4;    // 0,4,8,12
    const int brow = tid / 32;         // 0..7
    const int bcol = (tid % 32) * 4;   // 0..124

    float acc[8][8];
    #pragma unroll
    for (int i = 0; i < 8; i++)
        #pragma unroll
        for (int j = 0; j < 8; j++) acc[i][j] = 0.f;

    for (int k0 = 0; k0 < K; k0 += 16) {
        #pragma unroll
        for (int r = 0; r < 128; r += 64) {
            float4 v = *(const float4*)(A + (size_t)(bm0 + arow + r) * K + k0 + acol);
            As[acol + 0][arow + r] = v.x;
            As[acol + 1][arow + r] = v.y;
            As[acol + 2][arow + r] = v.z;
            As[acol + 3][arow + r] = v.w;
        }
        #pragma unroll
        for (int r = 0; r < 16; r += 8) {
            float4 v = *(const float4*)(W + (size_t)(k0 + brow + r) * N + bn0 + bcol);
            *(float4*)&Bs[brow + r][bcol] = v;
        }
        __syncthreads();
        #pragma unroll
        for (int k = 0; k < 16; k++) {
            float a[8], b[8];
            *(float4*)&a[0] = *(const float4*)&As[k][tm];
            *(float4*)&a[4] = *(const float4*)&As[k][tm + 4];
            *(float4*)&b[0] = *(const float4*)&Bs[k][tn];
            *(float4*)&b[4] = *(const float4*)&Bs[k][tn + 4];
            #pragma unroll
            for (int i = 0; i < 8; i++)
                #pragma unroll
                for (int j = 0; j < 8; j++) acc[i][j] += a[i] * b[j];
        }
        __syncthreads();
    }

    float bb[8];
    *(float4*)&bb[0] = *(const float4*)(bias + bn0 + tn);
    *(float4*)&bb[4] = *(const float4*)(bias + bn0 + tn + 4);
    #pragma unroll
    for (int i = 0; i < 8; i++) {
        float* crow = C + (size_t)(bm0 + tm + i) * N + bn0 + tn;
        float4 o0, o1;
        o0.x = tanhf(acc[i][0] + bb[0]); o0.y = tanhf(acc[i][1] + bb[1]);
        o0.z = tanhf(acc[i][2] + bb[2]); o0.w = tanhf(acc[i][3] + bb[3]);
        o1.x = tanhf(acc[i][4] + bb[4]); o1.y = tanhf(acc[i][5] + bb[5]);
        o1.z = tanhf(acc[i][6] + bb[6]); o1.w = tanhf(acc[i][7] + bb[7]);
        *(float4*)(crow)     = o0;
        *(float4*)(crow + 4) = o1;
    }
}

// ---------------- final layer: sigmoid(h4 @ W5 + b5), N=1 -------------------
__global__ void k_final(const float* __restrict__ h4, const float* __restrict__ W5,
                        const float* __restrict__ b5, float* __restrict__ out) {
    int gtid = blockIdx.x * blockDim.x + threadIdx.x;
    int row = gtid >> 5;
    int lane = gtid & 31;
    if (row >= N_NODES) return;
    const float4* a = (const float4*)(h4 + (size_t)row * (HID / 4));
    const float4* w = (const float4*)W5;
    float s = 0.f;
    #pragma unroll
    for (int i = 0; i < 2; i++) {
        int v4 = lane + i * 32;                    // 64 float4 total
        float4 x = a[v4], y = w[v4];
        s += x.x * y.x + x.y * y.y + x.z * y.z + x.w * y.w;
    }
    #pragma unroll
    for (int o = 16; o; o >>= 1) s += __shfl_xor_sync(0xffffffffu, s, o);
    if (lane == 0) out[row] = 1.f / (1.f + expf(-(s + b5[0])));
}

// ---------------- launcher ---------------------------------------------------
extern "C" void kernel_launch(void* const* d_in, const int* in_sizes, int n_in,
                              void* d_out, int out_size) {
    const float* H  = (const float*)d_in[0];
    const float* Ro = (const float*)d_in[1];
    const float* Ri = (const float*)d_in[2];
    const float* e  = (const float*)d_in[3];
    const float* W1 = (const float*)d_in[4];   const float* b1 = (const float*)d_in[5];
    const float* W2 = (const float*)d_in[6];   const float* b2 = (const float*)d_in[7];
    const float* W3 = (const float*)d_in[8];   const float* b3 = (const float*)d_in[9];
    const float* W4 = (const float*)d_in[10];  const float* b4 = (const float*)d_in[11];
    const float* W5 = (const float*)d_in[12];  const float* b5 = (const float*)d_in[13];
    float* out = (float*)d_out;

    float *p_eH, *p_Ho, *p_Hi, *p_x, *p_h1, *p_h2, *p_h3, *p_h4;
    int *p_src, *p_dst;
    cudaGetSymbolAddress((void**)&p_eH, g_eH);
    cudaGetSymbolAddress((void**)&p_Ho, g_Ho);
    cudaGetSymbolAddress((void**)&p_Hi, g_Hi);
    cudaGetSymbolAddress((void**)&p_x,  g_x);
    cudaGetSymbolAddress((void**)&p_h1, g_h1);
    cudaGetSymbolAddress((void**)&p_h2, g_h2);
    cudaGetSymbolAddress((void**)&p_h3, g_h3);
    cudaGetSymbolAddress((void**)&p_h4, g_h4);
    cudaGetSymbolAddress((void**)&p_src, g_src);
    cudaGetSymbolAddress((void**)&p_dst, g_dst);
    (void)p_src; (void)p_dst; (void)in_sizes; (void)n_in; (void)out_size;

    // 1) eH = e*H; zero Ho/Hi
    k_prep<<<(N_NODES * D_IN / 4 + 255) / 256, 256>>>(H, e);
    // 2) extract src/dst from one-hot rows (the 512MB scan)
    k_extract<<<dim3(N_EDGES, 2), 128>>>(Ro, Ri);
    // 3) scatter per edge
    k_scatter<<<(N_EDGES * 32 + 255) / 256, 256>>>();
    // 4) x = [Ho, H, Hi]
    k_concat<<<(N_NODES * 96 + 255) / 256, 256>>>(H);
    // 5) MLP
    k_gemm_tanh<<<dim3(HID / 128, N_NODES / 128), 256>>>(p_x,  W1, b1, p_h1, N_NODES, HID,     3 * D_IN);
    k_gemm_tanh<<<dim3(HID / 128, N_NODES / 128), 256>>>(p_h1, W2, b2, p_h2, N_NODES, HID,     HID);
    k_gemm_tanh<<<dim3(HID / 256, N_NODES / 128), 256>>>(p_h2, W3, b3, p_h3, N_NODES, HID / 2, HID);
    k_gemm_tanh<<<dim3(HID / 512, N_NODES / 128), 256>>>(p_h3, W4, b4, p_h4, N_NODES, HID / 4, HID / 2);
    // 6) final sigmoid head
    k_final<<<(N_NODES * 32 + 255) / 256, 256>>>(p_h4, W5, b5, out);
}

// round 3
// speedup vs baseline: 2.0030x; 2.0030x over previous
#include <cuda_runtime.h>
#include <cuda_bf16.h>
#include <math.h>
#include <stdint.h>

#define N_NODES 4096
#define N_EDGES 16384
#define D_IN    128
#define HID     1024

// ---------------- scratch (device globals; no allocation allowed) ----------
__device__ float g_eH[N_NODES * D_IN];
__device__ float g_Ho[N_NODES * D_IN];
__device__ float g_Hi[N_NODES * D_IN];
__device__ int   g_src[N_EDGES];
__device__ int   g_dst[N_EDGES];
__device__ float g_x [N_NODES * 3 * D_IN];
__device__ float g_h1[N_NODES * HID];
__device__ float g_h2[N_NODES * HID];
__device__ float g_h3[N_NODES * (HID / 2)];
__device__ float g_h4[N_NODES * (HID / 4)];
// transposed + bf16-split weights: W{n}hi/lo are [N,K] row-major bf16
__device__ __nv_bfloat16 g_W1hi[HID * 3 * D_IN],    g_W1lo[HID * 3 * D_IN];
__device__ __nv_bfloat16 g_W2hi[HID * HID],         g_W2lo[HID * HID];
__device__ __nv_bfloat16 g_W3hi[(HID/2) * HID],     g_W3lo[(HID/2) * HID];
__device__ __nv_bfloat16 g_W4hi[(HID/4) * (HID/2)], g_W4lo[(HID/4) * (HID/2)];

// ---------------- kernel 1: eH = e*H, zero Ho/Hi ---------------------------
__global__ void k_prep(const float* __restrict__ H, const float* __restrict__ e) {
    int idx = blockIdx.x * blockDim.x + threadIdx.x;
    const int total4 = N_NODES * D_IN / 4;
    if (idx >= total4) return;
    int node = idx / (D_IN / 4);
    float ev = e[node];
    float4 h = ((const float4*)H)[idx];
    ((float4*)g_eH)[idx] = make_float4(ev * h.x, ev * h.y, ev * h.z, ev * h.w);
    float4 z = make_float4(0.f, 0.f, 0.f, 0.f);
    ((float4*)g_Ho)[idx] = z;
    ((float4*)g_Hi)[idx] = z;
}

// ---------------- kernel 2: one-hot -> index, with early exit ---------------
__global__ void k_extract(const float* __restrict__ Ro, const float* __restrict__ Ri) {
    __shared__ int found;
    int e = blockIdx.x;
    const float* row = (blockIdx.y == 0 ? Ro : Ri) + (size_t)e * N_NODES;
    int* out = (blockIdx.y == 0 ? g_src : g_dst);
    if (threadIdx.x == 0) found = 0;
    __syncthreads();
    int t = threadIdx.x;
    #pragma unroll 1
    for (int i = 0; i < 8; i++) {
        int v4 = t + i * 128;
        float4 v = ((const float4*)row)[v4];
        if (v.x != 0.f || v.y != 0.f || v.z != 0.f || v.w != 0.f) {
            int base = v4 * 4;
            int col = (v.x != 0.f) ? base : (v.y != 0.f) ? base + 1
                    : (v.z != 0.f) ? base + 2 : base + 3;
            out[e] = col;
            found = 1;
        }
        __syncthreads();
        if (found) return;
    }
}

// ---------------- kernel 3: edge scatter ------------------------------------
__global__ void k_scatter() {
    int gtid = blockIdx.x * blockDim.x + threadIdx.x;
    int warp = gtid >> 5;
    int lane = gtid & 31;
    if (warp >= N_EDGES) return;
    int s = g_src[warp];
    int d = g_dst[warp];
    float4 vs = ((const float4*)(g_eH + (size_t)s * D_IN))[lane];
    float4 vd = ((const float4*)(g_eH + (size_t)d * D_IN))[lane];
    float* ho = g_Ho + (size_t)d * D_IN + lane * 4;
    float* hi = g_Hi + (size_t)s * D_IN + lane * 4;
    atomicAdd(ho + 0, vs.x); atomicAdd(ho + 1, vs.y);
    atomicAdd(ho + 2, vs.z); atomicAdd(ho + 3, vs.w);
    atomicAdd(hi + 0, vd.x); atomicAdd(hi + 1, vd.y);
    atomicAdd(hi + 2, vd.z); atomicAdd(hi + 3, vd.w);
}

// ---------------- kernel 4: x = concat(Ho, H, Hi) ---------------------------
__global__ void k_concat(const float* __restrict__ H) {
    int idx = blockIdx.x * blockDim.x + threadIdx.x;
    const int per_row4 = 3 * D_IN / 4;
    const int total4 = N_NODES * per_row4;
    if (idx >= total4) return;
    int node = idx / per_row4;
    int c4 = idx - node * per_row4;
    float4 v;
    if (c4 < 32)       v = ((const float4*)(g_Ho + (size_t)node * D_IN))[c4];
    else if (c4 < 64)  v = ((const float4*)(H    + (size_t)node * D_IN))[c4 - 32];
    else               v = ((const float4*)(g_Hi + (size_t)node * D_IN))[c4 - 64];
    ((float4*)g_x)[idx] = v;
}

// ---------------- weight transpose + bf16 hi/lo split ------------------------
// W is [K,N] row-major fp32; output hi/lo are [N,K] row-major bf16.
__global__ void k_wsplit(const float* __restrict__ W, __nv_bfloat16* __restrict__ hi,
                         __nv_bfloat16* __restrict__ lo, int K, int N) {
    __shared__ float t[32][33];
    int bx = blockIdx.x * 32, by = blockIdx.y * 32;
    int x = threadIdx.x, y = threadIdx.y;
    #pragma unroll
    for (int j = 0; j < 32; j += 8)
        t[y + j][x] = W[(size_t)(by + y + j) * N + bx + x];
    __syncthreads();
    #pragma unroll
    for (int j = 0; j < 32; j += 8) {
        int n = bx + y + j, k = by + x;
        float v = t[x][y + j];
        __nv_bfloat16 h = __float2bfloat16(v);
        hi[(size_t)n * K + k] = h;
        lo[(size_t)n * K + k] = __float2bfloat16(v - __bfloat162float(h));
    }
}

// ---------------- mma.sync GEMM: C = tanh(A @ W + b) -------------------------
// A [M,K] fp32 (split to bf16 hi/lo on load), B = Whi/Wlo [N,K] bf16.
// CTA 128x128, warp 32x64, K-chunk 64, bf16x3 into fp32 accumulators.
// smem rows padded to 72 bf16 (144 B) -> conflict-free ldmatrix.
#define SROW 72
#define SROWB 144
#define OFF_AHI 0
#define OFF_ALO (128 * SROWB)
#define OFF_BHI (2 * 128 * SROWB)
#define OFF_BLO (3 * 128 * SROWB)
#define GEMM_SMEM (4 * 128 * SROWB)

__device__ __forceinline__ uint32_t smem_u32(const void* p) {
    uint32_t a;
    asm("{ .reg .u64 t; cvta.to.shared.u64 t, %1; cvt.u32.u64 %0, t; }" : "=r"(a) : "l"(p));
    return a;
}
#define LDSM_X4(r0, r1, r2, r3, addr) \
    asm volatile("ldmatrix.sync.aligned.m8n8.x4.shared.b16 {%0,%1,%2,%3}, [%4];" \
                 : "=r"(r0), "=r"(r1), "=r"(r2), "=r"(r3) : "r"(addr))

__device__ __forceinline__ void mma_bf16(float* c, const uint32_t* a, const uint32_t* b) {
    asm volatile(
        "mma.sync.aligned.m16n8k16.row.col.f32.bf16.bf16.f32 "
        "{%0,%1,%2,%3}, {%4,%5,%6,%7}, {%8,%9}, {%0,%1,%2,%3};"
        : "+f"(c[0]), "+f"(c[1]), "+f"(c[2]), "+f"(c[3])
        : "r"(a[0]), "r"(a[1]), "r"(a[2]), "r"(a[3]), "r"(b[0]), "r"(b[1]));
}

__global__ void __launch_bounds__(256, 1)
k_gemm_mma(const float* __restrict__ A, const __nv_bfloat16* __restrict__ Bhi,
           const __nv_bfloat16* __restrict__ Blo, const float* __restrict__ bias,
           float* __restrict__ C, int N, int K) {
    extern __shared__ char smem[];
    const uint32_t sb = smem_u32(smem);
    const int tid = threadIdx.x;
    const int wid = tid >> 5;
    const int lane = tid & 31;
    const int wm = wid & 3;          // warp M block (32 rows)
    const int wn = wid >> 2;         // warp N block (64 cols)
    const int bm0 = blockIdx.y * 128;
    const int bn0 = blockIdx.x * 128;

    float acc[2][8][4];
    #pragma unroll
    for (int mt = 0; mt < 2; mt++)
        #pragma unroll
        for (int j = 0; j < 8; j++)
            #pragma unroll
            for (int q = 0; q < 4; q++) acc[mt][j][q] = 0.f;

    // ldmatrix lane addressing
    const int a_row = wm * 32 + (lane & 15);              // + mt*16
    const int a_kof = (lane >> 4) * 8;                    // + ks
    const int b_row = wn * 64 + (lane & 7) + (lane >> 4) * 8;  // + jp*16
    const int b_kof = ((lane >> 3) & 1) * 8;              // + ks

    for (int k0 = 0; k0 < K; k0 += 64) {
        // ---- A chunk [128 x 64] fp32 -> bf16 hi/lo ----
        #pragma unroll
        for (int i = 0; i < 8; i++) {
            int idx = tid + i * 256;       // 0..2047 float4
            int row = idx >> 4;
            int c4 = idx & 15;
            float4 v = *(const float4*)(A + (size_t)(bm0 + row) * K + k0 + c4 * 4);
            __nv_bfloat162 h01 = __floats2bfloat162_rn(v.x, v.y);
            __nv_bfloat162 h23 = __floats2bfloat162_rn(v.z, v.w);
            float2 f01 = __bfloat1622float2(h01);
            float2 f23 = __bfloat1622float2(h23);
            __nv_bfloat162 l01 = __floats2bfloat162_rn(v.x - f01.x, v.y - f01.y);
            __nv_bfloat162 l23 = __floats2bfloat162_rn(v.z - f23.x, v.w - f23.y);
            uint32_t off = row * SROWB + c4 * 8;
            *(uint2*)(smem + OFF_AHI + off) = make_uint2(*(uint32_t*)&h01, *(uint32_t*)&h23);
            *(uint2*)(smem + OFF_ALO + off) = make_uint2(*(uint32_t*)&l01, *(uint32_t*)&l23);
        }
        // ---- B chunk [128 x 64] bf16 hi/lo ----
        #pragma unroll
        for (int i = 0; i < 4; i++) {
            int idx = tid + i * 256;       // 0..1023 (8-bf16 groups)
            int row = idx >> 3;
            int g = idx & 7;
            uint32_t off = row * SROWB + g * 16;
            size_t goff = (size_t)(bn0 + row) * K + k0 + g * 8;
            *(uint4*)(smem + OFF_BHI + off) = *(const uint4*)(Bhi + goff);
            *(uint4*)(smem + OFF_BLO + off) = *(const uint4*)(Blo + goff);
        }
        __syncthreads();

        #pragma unroll
        for (int ks = 0; ks < 64; ks += 16) {
            uint32_t ahi[2][4], alo[2][4], bhi[8][2], blo[8][2];
            #pragma unroll
            for (int mt = 0; mt < 2; mt++) {
                uint32_t ao = (a_row + mt * 16) * SROWB + (a_kof + ks) * 2;
                LDSM_X4(ahi[mt][0], ahi[mt][1], ahi[mt][2], ahi[mt][3], sb + OFF_AHI + ao);
                LDSM_X4(alo[mt][0], alo[mt][1], alo[mt][2], alo[mt][3], sb + OFF_ALO + ao);
            }
            #pragma unroll
            for (int jp = 0; jp < 4; jp++) {
                uint32_t bo = (b_row + jp * 16) * SROWB + (b_kof + ks) * 2;
                LDSM_X4(bhi[jp*2][0], bhi[jp*2][1], bhi[jp*2+1][0], bhi[jp*2+1][1], sb + OFF_BHI + bo);
                LDSM_X4(blo[jp*2][0], blo[jp*2][1], blo[jp*2+1][0], blo[jp*2+1][1], sb + OFF_BLO + bo);
            }
            #pragma unroll
            for (int mt = 0; mt < 2; mt++)
                #pragma unroll
                for (int j = 0; j < 8; j++) {
                    mma_bf16(acc[mt][j], ahi[mt], bhi[j]);
                    mma_bf16(acc[mt][j], ahi[mt], blo[j]);
                    mma_bf16(acc[mt][j], alo[mt], bhi[j]);
                }
        }
        __syncthreads();
    }

    // ---- epilogue: bias + tanh ----
    const int g = lane >> 2, tig = lane & 3;
    #pragma unroll
    for (int mt = 0; mt < 2; mt++) {
        int row0 = bm0 + wm * 32 + mt * 16 + g;
        #pragma unroll
        for (int j = 0; j < 8; j++) {
            int col = bn0 + wn * 64 + j * 8 + tig * 2;
            float bc0 = __ldg(bias + col), bc1 = __ldg(bias + col + 1);
            float* c0 = C + (size_t)row0 * N + col;
            float* c1 = C + (size_t)(row0 + 8) * N + col;
            c0[0] = tanhf(acc[mt][j][0] + bc0);
            c0[1] = tanhf(acc[mt][j][1] + bc1);
            c1[0] = tanhf(acc[mt][j][2] + bc0);
            c1[1] = tanhf(acc[mt][j][3] + bc1);
        }
    }
}

// ---------------- final layer: sigmoid(h4 @ W5 + b5), N=1 -------------------
__global__ void k_final(const float* __restrict__ h4, const float* __restrict__ W5,
                        const float* __restrict__ b5, float* __restrict__ out) {
    int gtid = blockIdx.x * blockDim.x + threadIdx.x;
    int row = gtid >> 5;
    int lane = gtid & 31;
    if (row >= N_NODES) return;
    const float4* a = (const float4*)(h4 + (size_t)row * (HID / 4));
    const float4* w = (const float4*)W5;
    float s = 0.f;
    #pragma unroll
    for (int i = 0; i < 2; i++) {
        int v4 = lane + i * 32;
        float4 x = a[v4], y = w[v4];
        s += x.x * y.x + x.y * y.y + x.z * y.z + x.w * y.w;
    }
    #pragma unroll
    for (int o = 16; o; o >>= 1) s += __shfl_xor_sync(0xffffffffu, s, o);
    if (lane == 0) out[row] = 1.f / (1.f + expf(-(s + b5[0])));
}

// ---------------- launcher ---------------------------------------------------
extern "C" void kernel_launch(void* const* d_in, const int* in_sizes, int n_in,
                              void* d_out, int out_size) {
    const float* H  = (const float*)d_in[0];
    const float* Ro = (const float*)d_in[1];
    const float* Ri = (const float*)d_in[2];
    const float* e  = (const float*)d_in[3];
    const float* W1 = (const float*)d_in[4];   const float* b1 = (const float*)d_in[5];
    const float* W2 = (const float*)d_in[6];   const float* b2 = (const float*)d_in[7];
    const float* W3 = (const float*)d_in[8];   const float* b3 = (const float*)d_in[9];
    const float* W4 = (const float*)d_in[10];  const float* b4 = (const float*)d_in[11];
    const float* W5 = (const float*)d_in[12];  const float* b5 = (const float*)d_in[13];
    float* out = (float*)d_out;
    (void)in_sizes; (void)n_in; (void)out_size;

    float *p_x, *p_h1, *p_h2, *p_h3, *p_h4;
    __nv_bfloat16 *w1h, *w1l, *w2h, *w2l, *w3h, *w3l, *w4h, *w4l;
    cudaGetSymbolAddress((void**)&p_x,  g_x);
    cudaGetSymbolAddress((void**)&p_h1, g_h1);
    cudaGetSymbolAddress((void**)&p_h2, g_h2);
    cudaGetSymbolAddress((void**)&p_h3, g_h3);
    cudaGetSymbolAddress((void**)&p_h4, g_h4);
    cudaGetSymbolAddress((void**)&w1h, g_W1hi); cudaGetSymbolAddress((void**)&w1l, g_W1lo);
    cudaGetSymbolAddress((void**)&w2h, g_W2hi); cudaGetSymbolAddress((void**)&w2l, g_W2lo);
    cudaGetSymbolAddress((void**)&w3h, g_W3hi); cudaGetSymbolAddress((void**)&w3l, g_W3lo);
    cudaGetSymbolAddress((void**)&w4h, g_W4hi); cudaGetSymbolAddress((void**)&w4l, g_W4lo);

    cudaFuncSetAttribute(k_gemm_mma, cudaFuncAttributeMaxDynamicSharedMemorySize, GEMM_SMEM);

    // prep + weight split (independent front-end work)
    k_prep<<<(N_NODES * D_IN / 4 + 255) / 256, 256>>>(H, e);
    k_wsplit<<<dim3(HID / 32, 3 * D_IN / 32), dim3(32, 8)>>>(W1, w1h, w1l, 3 * D_IN, HID);
    k_wsplit<<<dim3(HID / 32, HID / 32),      dim3(32, 8)>>>(W2, w2h, w2l, HID, HID);
    k_wsplit<<<dim3(HID / 64, HID / 32),      dim3(32, 8)>>>(W3, w3h, w3l, HID, HID / 2);
    k_wsplit<<<dim3(HID / 128, HID / 64),     dim3(32, 8)>>>(W4, w4h, w4l, HID / 2, HID / 4);
    // one-hot scan + scatter + concat
    k_extract<<<dim3(N_EDGES, 2), 128>>>(Ro, Ri);
    k_scatter<<<(N_EDGES * 32 + 255) / 256, 256>>>();
    k_concat<<<(N_NODES * 96 + 255) / 256, 256>>>(H);
    // MLP on tensor cores via mma.sync (bf16x3, fp32 accumulate)
    k_gemm_mma<<<dim3(HID / 128,     N_NODES / 128), 256, GEMM_SMEM>>>(p_x,  w1h, w1l, b1, p_h1, HID,     3 * D_IN);
    k_gemm_mma<<<dim3(HID / 128,     N_NODES / 128), 256, GEMM_SMEM>>>(p_h1, w2h, w2l, b2, p_h2, HID,     HID);
    k_gemm_mma<<<dim3(HID / 2 / 128, N_NODES / 128), 256, GEMM_SMEM>>>(p_h2, w3h, w3l, b3, p_h3, HID / 2, HID);
    k_gemm_mma<<<dim3(HID / 4 / 128, N_NODES / 128), 256, GEMM_SMEM>>>(p_h3, w4h, w4l, b4, p_h4, HID / 4, HID / 2);
    // head
    k_final<<<(N_NODES * 32 + 255) / 256, 256>>>(p_h4, W5, b5, out);
}

// round 4
// speedup vs baseline: 2.4168x; 1.2066x over previous
#include <cuda_runtime.h>
#include <cuda_bf16.h>
#include <math.h>
#include <stdint.h>

#define N_NODES 4096
#define N_EDGES 16384
#define D_IN    128
#define HID     1024

// ---------------- scratch (device globals; no allocation allowed) ----------
__device__ float g_eH[N_NODES * D_IN];
__device__ float g_Ho[N_NODES * D_IN];
__device__ float g_Hi[N_NODES * D_IN];
__device__ int   g_src[N_EDGES];
__device__ int   g_dst[N_EDGES];
__device__ float g_h4[N_NODES * (HID / 4)];
// activations as bf16 hi/lo pairs
__device__ __nv_bfloat16 g_xhi[N_NODES * 3 * D_IN],  g_xlo[N_NODES * 3 * D_IN];
__device__ __nv_bfloat16 g_h1hi[N_NODES * HID],      g_h1lo[N_NODES * HID];
__device__ __nv_bfloat16 g_h2hi[N_NODES * HID],      g_h2lo[N_NODES * HID];
__device__ __nv_bfloat16 g_h3hi[N_NODES * (HID/2)],  g_h3lo[N_NODES * (HID/2)];
// transposed + bf16-split weights: [N,K] row-major
__device__ __nv_bfloat16 g_W1hi[HID * 3 * D_IN],    g_W1lo[HID * 3 * D_IN];
__device__ __nv_bfloat16 g_W2hi[HID * HID],         g_W2lo[HID * HID];
__device__ __nv_bfloat16 g_W3hi[(HID/2) * HID],     g_W3lo[(HID/2) * HID];
__device__ __nv_bfloat16 g_W4hi[(HID/4) * (HID/2)], g_W4lo[(HID/4) * (HID/2)];

// ---------------- kernel 1: eH = e*H, zero Ho/Hi ---------------------------
__global__ void k_prep(const float* __restrict__ H, const float* __restrict__ e) {
    int idx = blockIdx.x * blockDim.x + threadIdx.x;
    const int total4 = N_NODES * D_IN / 4;
    if (idx >= total4) return;
    int node = idx / (D_IN / 4);
    float ev = e[node];
    float4 h = ((const float4*)H)[idx];
    ((float4*)g_eH)[idx] = make_float4(ev * h.x, ev * h.y, ev * h.z, ev * h.w);
    float4 z = make_float4(0.f, 0.f, 0.f, 0.f);
    ((float4*)g_Ho)[idx] = z;
    ((float4*)g_Hi)[idx] = z;
}

// ---------------- kernel 2: one-hot -> index, with early exit ---------------
__global__ void k_extract(const float* __restrict__ Ro, const float* __restrict__ Ri) {
    __shared__ int found;
    int e = blockIdx.x;
    const float* row = (blockIdx.y == 0 ? Ro : Ri) + (size_t)e * N_NODES;
    int* out = (blockIdx.y == 0 ? g_src : g_dst);
    if (threadIdx.x == 0) found = 0;
    __syncthreads();
    int t = threadIdx.x;
    #pragma unroll 1
    for (int i = 0; i < 8; i++) {
        int v4 = t + i * 128;
        float4 v = ((const float4*)row)[v4];
        if (v.x != 0.f || v.y != 0.f || v.z != 0.f || v.w != 0.f) {
            int base = v4 * 4;
            int col = (v.x != 0.f) ? base : (v.y != 0.f) ? base + 1
                    : (v.z != 0.f) ? base + 2 : base + 3;
            out[e] = col;
            found = 1;
        }
        __syncthreads();
        if (found) return;
    }
}

// ---------------- kernel 3: edge scatter ------------------------------------
__global__ void k_scatter() {
    int gtid = blockIdx.x * blockDim.x + threadIdx.x;
    int warp = gtid >> 5;
    int lane = gtid & 31;
    if (warp >= N_EDGES) return;
    int s = g_src[warp];
    int d = g_dst[warp];
    float4 vs = ((const float4*)(g_eH + (size_t)s * D_IN))[lane];
    float4 vd = ((const float4*)(g_eH + (size_t)d * D_IN))[lane];
    float* ho = g_Ho + (size_t)d * D_IN + lane * 4;
    float* hi = g_Hi + (size_t)s * D_IN + lane * 4;
    atomicAdd(ho + 0, vs.x); atomicAdd(ho + 1, vs.y);
    atomicAdd(ho + 2, vs.z); atomicAdd(ho + 3, vs.w);
    atomicAdd(hi + 0, vd.x); atomicAdd(hi + 1, vd.y);
    atomicAdd(hi + 2, vd.z); atomicAdd(hi + 3, vd.w);
}

// ---------------- kernel 4: x = concat(Ho, H, Hi) -> bf16 hi/lo --------------
__global__ void k_concat(const float* __restrict__ H) {
    int idx = blockIdx.x * blockDim.x + threadIdx.x;
    const int per_row4 = 3 * D_IN / 4;
    const int total4 = N_NODES * per_row4;
    if (idx >= total4) return;
    int node = idx / per_row4;
    int c4 = idx - node * per_row4;
    float4 v;
    if (c4 < 32)       v = ((const float4*)(g_Ho + (size_t)node * D_IN))[c4];
    else if (c4 < 64)  v = ((const float4*)(H    + (size_t)node * D_IN))[c4 - 32];
    else               v = ((const float4*)(g_Hi + (size_t)node * D_IN))[c4 - 64];
    __nv_bfloat162 h01 = __floats2bfloat162_rn(v.x, v.y);
    __nv_bfloat162 h23 = __floats2bfloat162_rn(v.z, v.w);
    float2 f01 = __bfloat1622float2(h01);
    float2 f23 = __bfloat1622float2(h23);
    __nv_bfloat162 l01 = __floats2bfloat162_rn(v.x - f01.x, v.y - f01.y);
    __nv_bfloat162 l23 = __floats2bfloat162_rn(v.z - f23.x, v.w - f23.y);
    size_t off = (size_t)node * (3 * D_IN) + c4 * 4;
    *(uint2*)(g_xhi + off) = make_uint2(*(uint32_t*)&h01, *(uint32_t*)&h23);
    *(uint2*)(g_xlo + off) = make_uint2(*(uint32_t*)&l01, *(uint32_t*)&l23);
}

// ---------------- weight transpose + bf16 hi/lo split ------------------------
__global__ void k_wsplit(const float* __restrict__ W, __nv_bfloat16* __restrict__ hi,
                         __nv_bfloat16* __restrict__ lo, int K, int N) {
    __shared__ float t[32][33];
    int bx = blockIdx.x * 32, by = blockIdx.y * 32;
    int x = threadIdx.x, y = threadIdx.y;
    #pragma unroll
    for (int j = 0; j < 32; j += 8)
        t[y + j][x] = W[(size_t)(by + y + j) * N + bx + x];
    __syncthreads();
    #pragma unroll
    for (int j = 0; j < 32; j += 8) {
        int n = bx + y + j, k = by + x;
        float v = t[x][y + j];
        __nv_bfloat16 h = __float2bfloat16(v);
        hi[(size_t)n * K + k] = h;
        lo[(size_t)n * K + k] = __float2bfloat16(v - __bfloat162float(h));
    }
}

// ---------------- pipelined mma.sync GEMM -----------------------------------
// A = Ahi/Alo [M,K] bf16, B = Bhi/Blo [N,K] bf16. CTA 128x128, K-chunk 64,
// 3-stage cp.async pipeline, XOR-swizzled 128B smem rows, bf16x3 -> fp32 acc.
// SPLIT_OUT: write tanh(out) as bf16 hi/lo; else fp32.
#define TILE_B 16384
#define STAGE_B (4 * TILE_B)
#define GEMM_SMEM (3 * STAGE_B)
#define OFF_AHI 0
#define OFF_ALO TILE_B
#define OFF_BHI (2 * TILE_B)
#define OFF_BLO (3 * TILE_B)

__device__ __forceinline__ uint32_t smem_u32(const void* p) {
    uint32_t a;
    asm("{ .reg .u64 t; cvta.to.shared.u64 t, %1; cvt.u32.u64 %0, t; }" : "=r"(a) : "l"(p));
    return a;
}
#define SWZ(row, kg) (((row) << 7) + ((((kg) ^ ((row) & 7))) << 4))
#define CP_ASYNC16(dst, src) \
    asm volatile("cp.async.cg.shared.global [%0], [%1], 16;" :: "r"(dst), "l"(src))
#define CP_COMMIT() asm volatile("cp.async.commit_group;" ::: "memory")
#define CP_WAIT2()  asm volatile("cp.async.wait_group 2;" ::: "memory")
#define LDSM_X4(r0, r1, r2, r3, addr) \
    asm volatile("ldmatrix.sync.aligned.m8n8.x4.shared.b16 {%0,%1,%2,%3}, [%4];" \
                 : "=r"(r0), "=r"(r1), "=r"(r2), "=r"(r3) : "r"(addr))

__device__ __forceinline__ void mma_bf16(float* c, const uint32_t* a, const uint32_t* b) {
    asm volatile(
        "mma.sync.aligned.m16n8k16.row.col.f32.bf16.bf16.f32 "
        "{%0,%1,%2,%3}, {%4,%5,%6,%7}, {%8,%9}, {%0,%1,%2,%3};"
        : "+f"(c[0]), "+f"(c[1]), "+f"(c[2]), "+f"(c[3])
        : "r"(a[0]), "r"(a[1]), "r"(a[2]), "r"(a[3]), "r"(b[0]), "r"(b[1]));
}

template <bool SPLIT_OUT>
__global__ void __launch_bounds__(256, 1)
k_gemm(const __nv_bfloat16* __restrict__ Ahi, const __nv_bfloat16* __restrict__ Alo,
       const __nv_bfloat16* __restrict__ Bhi, const __nv_bfloat16* __restrict__ Blo,
       const float* __restrict__ bias,
       __nv_bfloat16* __restrict__ Chi, __nv_bfloat16* __restrict__ Clo,
       float* __restrict__ Cf, int N, int K) {
    extern __shared__ char smem[];
    const uint32_t sb = smem_u32(smem);
    const int tid = threadIdx.x;
    const int wid = tid >> 5;
    const int lane = tid & 31;
    const int wm = wid & 3;
    const int wn = wid >> 2;
    const int bm0 = blockIdx.y * 128;
    const int bn0 = blockIdx.x * 128;
    const int nch = K >> 6;

    float acc[2][8][4];
    #pragma unroll
    for (int mt = 0; mt < 2; mt++)
        #pragma unroll
        for (int j = 0; j < 8; j++)
            #pragma unroll
            for (int q = 0; q < 4; q++) acc[mt][j][q] = 0.f;

    // per-thread load mapping: 4 iters x (row = idx>>3, kg = idx&7)
    int l_row[4], l_kg[4];
    #pragma unroll
    for (int i = 0; i < 4; i++) {
        int idx = tid + i * 256;
        l_row[i] = idx >> 3;
        l_kg[i] = idx & 7;
    }

    auto issue = [&](int c, int buf) {
        uint32_t base = sb + buf * STAGE_B;
        int k0 = c << 6;
        #pragma unroll
        for (int i = 0; i < 4; i++) {
            int row = l_row[i], kg = l_kg[i];
            uint32_t d = base + SWZ(row, kg);
            size_t ka = (size_t)(bm0 + row) * K + k0 + kg * 8;
            size_t kb = (size_t)(bn0 + row) * K + k0 + kg * 8;
            CP_ASYNC16(d + OFF_AHI, Ahi + ka);
            CP_ASYNC16(d + OFF_ALO, Alo + ka);
            CP_ASYNC16(d + OFF_BHI, Bhi + kb);
            CP_ASYNC16(d + OFF_BLO, Blo + kb);
        }
    };

    // prologue: stages 0,1
    issue(0, 0); CP_COMMIT();
    issue(1, 1); CP_COMMIT();

    const int a_row = wm * 32 + (lane & 15);
    const int a_kg  = lane >> 4;
    const int b_row = wn * 64 + (lane & 7) + (lane >> 4) * 8;
    const int b_kg  = (lane >> 3) & 1;

    int buf = 0;
    for (int i = 0; i < nch; i++) {
        int c = i + 2;
        if (c < nch) issue(c, c % 3);
        CP_COMMIT();
        CP_WAIT2();
        __syncthreads();

        uint32_t sbase = sb + buf * STAGE_B;
        #pragma unroll
        for (int ks8 = 0; ks8 < 8; ks8 += 2) {
            uint32_t ahi[2][4], alo[2][4], bhi[8][2], blo[8][2];
            #pragma unroll
            for (int mt = 0; mt < 2; mt++) {
                int row = a_row + mt * 16, kg = a_kg + ks8;
                uint32_t ad = sbase + OFF_AHI + SWZ(row, kg);
                LDSM_X4(ahi[mt][0], ahi[mt][1], ahi[mt][2], ahi[mt][3], ad);
                LDSM_X4(alo[mt][0], alo[mt][1], alo[mt][2], alo[mt][3], ad + TILE_B);
            }
            #pragma unroll
            for (int jp = 0; jp < 4; jp++) {
                int row = b_row + jp * 16, kg = b_kg + ks8;
                uint32_t bd = sbase + OFF_BHI + SWZ(row, kg);
                LDSM_X4(bhi[jp*2][0], bhi[jp*2][1], bhi[jp*2+1][0], bhi[jp*2+1][1], bd);
                LDSM_X4(blo[jp*2][0], blo[jp*2][1], blo[jp*2+1][0], blo[jp*2+1][1], bd + TILE_B);
            }
            #pragma unroll
            for (int mt = 0; mt < 2; mt++)
                #pragma unroll
                for (int j = 0; j < 8; j++) {
                    mma_bf16(acc[mt][j], ahi[mt], bhi[j]);
                    mma_bf16(acc[mt][j], ahi[mt], blo[j]);
                    mma_bf16(acc[mt][j], alo[mt], bhi[j]);
                }
        }
        __syncthreads();
        buf = (buf == 2) ? 0 : buf + 1;
    }

    // ---- epilogue: bias + tanh (+ optional hi/lo split) ----
    const int g = lane >> 2, tig = lane & 3;
    #pragma unroll
    for (int mt = 0; mt < 2; mt++) {
        int row0 = bm0 + wm * 32 + mt * 16 + g;
        #pragma unroll
        for (int j = 0; j < 8; j++) {
            int col = bn0 + wn * 64 + j * 8 + tig * 2;
            float bc0 = __ldg(bias + col), bc1 = __ldg(bias + col + 1);
            float v00 = tanhf(acc[mt][j][0] + bc0);
            float v01 = tanhf(acc[mt][j][1] + bc1);
            float v10 = tanhf(acc[mt][j][2] + bc0);
            float v11 = tanhf(acc[mt][j][3] + bc1);
            if (SPLIT_OUT) {
                __nv_bfloat162 h0 = __floats2bfloat162_rn(v00, v01);
                __nv_bfloat162 h1 = __floats2bfloat162_rn(v10, v11);
                float2 f0 = __bfloat1622float2(h0);
                float2 f1 = __bfloat1622float2(h1);
                __nv_bfloat162 l0 = __floats2bfloat162_rn(v00 - f0.x, v01 - f0.y);
                __nv_bfloat162 l1 = __floats2bfloat162_rn(v10 - f1.x, v11 - f1.y);
                *(uint32_t*)(Chi + (size_t)row0 * N + col)       = *(uint32_t*)&h0;
                *(uint32_t*)(Clo + (size_t)row0 * N + col)       = *(uint32_t*)&l0;
                *(uint32_t*)(Chi + (size_t)(row0 + 8) * N + col) = *(uint32_t*)&h1;
                *(uint32_t*)(Clo + (size_t)(row0 + 8) * N + col) = *(uint32_t*)&l1;
            } else {
                *(float2*)(Cf + (size_t)row0 * N + col)       = make_float2(v00, v01);
                *(float2*)(Cf + (size_t)(row0 + 8) * N + col) = make_float2(v10, v11);
            }
        }
    }
}

// ---------------- final layer: sigmoid(h4 @ W5 + b5), N=1 -------------------
__global__ void k_final(const float* __restrict__ h4, const float* __restrict__ W5,
                        const float* __restrict__ b5, float* __restrict__ out) {
    int gtid = blockIdx.x * blockDim.x + threadIdx.x;
    int row = gtid >> 5;
    int lane = gtid & 31;
    if (row >= N_NODES) return;
    const float4* a = (const float4*)(h4 + (size_t)row * (HID / 4));
    const float4* w = (const float4*)W5;
    float s = 0.f;
    #pragma unroll
    for (int i = 0; i < 2; i++) {
        int v4 = lane + i * 32;
        float4 x = a[v4], y = w[v4];
        s += x.x * y.x + x.y * y.y + x.z * y.z + x.w * y.w;
    }
    #pragma unroll
    for (int o = 16; o; o >>= 1) s += __shfl_xor_sync(0xffffffffu, s, o);
    if (lane == 0) out[row] = 1.f / (1.f + expf(-(s + b5[0])));
}

// ---------------- launcher ---------------------------------------------------
extern "C" void kernel_launch(void* const* d_in, const int* in_sizes, int n_in,
                              void* d_out, int out_size) {
    const float* H  = (const float*)d_in[0];
    const float* Ro = (const float*)d_in[1];
    const float* Ri = (const float*)d_in[2];
    const float* e  = (const float*)d_in[3];
    const float* W1 = (const float*)d_in[4];   const float* b1 = (const float*)d_in[5];
    const float* W2 = (const float*)d_in[6];   const float* b2 = (const float*)d_in[7];
    const float* W3 = (const float*)d_in[8];   const float* b3 = (const float*)d_in[9];
    const float* W4 = (const float*)d_in[10];  const float* b4 = (const float*)d_in[11];
    const float* W5 = (const float*)d_in[12];  const float* b5 = (const float*)d_in[13];
    float* out = (float*)d_out;
    (void)in_sizes; (void)n_in; (void)out_size;

    __nv_bfloat16 *xh, *xl, *h1h, *h1l, *h2h, *h2l, *h3h, *h3l;
    __nv_bfloat16 *w1h, *w1l, *w2h, *w2l, *w3h, *w3l, *w4h, *w4l;
    float* p_h4;
    cudaGetSymbolAddress((void**)&xh, g_xhi);   cudaGetSymbolAddress((void**)&xl, g_xlo);
    cudaGetSymbolAddress((void**)&h1h, g_h1hi); cudaGetSymbolAddress((void**)&h1l, g_h1lo);
    cudaGetSymbolAddress((void**)&h2h, g_h2hi); cudaGetSymbolAddress((void**)&h2l, g_h2lo);
    cudaGetSymbolAddress((void**)&h3h, g_h3hi); cudaGetSymbolAddress((void**)&h3l, g_h3lo);
    cudaGetSymbolAddress((void**)&p_h4, g_h4);
    cudaGetSymbolAddress((void**)&w1h, g_W1hi); cudaGetSymbolAddress((void**)&w1l, g_W1lo);
    cudaGetSymbolAddress((void**)&w2h, g_W2hi); cudaGetSymbolAddress((void**)&w2l, g_W2lo);
    cudaGetSymbolAddress((void**)&w3h, g_W3hi); cudaGetSymbolAddress((void**)&w3l, g_W3lo);
    cudaGetSymbolAddress((void**)&w4h, g_W4hi); cudaGetSymbolAddress((void**)&w4l, g_W4lo);

    cudaFuncSetAttribute(k_gemm<true>,  cudaFuncAttributeMaxDynamicSharedMemorySize, GEMM_SMEM);
    cudaFuncSetAttribute(k_gemm<false>, cudaFuncAttributeMaxDynamicSharedMemorySize, GEMM_SMEM);

    // prep + weight split
    k_prep<<<(N_NODES * D_IN / 4 + 255) / 256, 256>>>(H, e);
    k_wsplit<<<dim3(HID / 32, 3 * D_IN / 32), dim3(32, 8)>>>(W1, w1h, w1l, 3 * D_IN, HID);
    k_wsplit<<<dim3(HID / 32, HID / 32),      dim3(32, 8)>>>(W2, w2h, w2l, HID, HID);
    k_wsplit<<<dim3(HID / 64, HID / 32),      dim3(32, 8)>>>(W3, w3h, w3l, HID, HID / 2);
    k_wsplit<<<dim3(HID / 128, HID / 64),     dim3(32, 8)>>>(W4, w4h, w4l, HID / 2, HID / 4);
    // one-hot scan + scatter + concat(split)
    k_extract<<<dim3(N_EDGES, 2), 128>>>(Ro, Ri);
    k_scatter<<<(N_EDGES * 32 + 255) / 256, 256>>>();
    k_concat<<<(N_NODES * 96 + 255) / 256, 256>>>(H);
    // MLP (bf16x3 on tensor pipes, cp.async pipelined)
    k_gemm<true><<<dim3(HID / 128,     N_NODES / 128), 256, GEMM_SMEM>>>(xh,  xl,  w1h, w1l, b1, h1h, h1l, nullptr, HID,     3 * D_IN);
    k_gemm<true><<<dim3(HID / 128,     N_NODES / 128), 256, GEMM_SMEM>>>(h1h, h1l, w2h, w2l, b2, h2h, h2l, nullptr, HID,     HID);
    k_gemm<true><<<dim3(HID / 2 / 128, N_NODES / 128), 256, GEMM_SMEM>>>(h2h, h2l, w3h, w3l, b3, h3h, h3l, nullptr, HID / 2, HID);
    k_gemm<false><<<dim3(HID / 4 / 128, N_NODES / 128), 256, GEMM_SMEM>>>(h3h, h3l, w4h, w4l, b4, nullptr, nullptr, p_h4, HID / 4, HID / 2);
    // head
    k_final<<<(N_NODES * 32 + 255) / 256, 256>>>(p_h4, W5, b5, out);
}

// round 5
// speedup vs baseline: 3.0901x; 1.2786x over previous
#include <cuda_runtime.h>
#include <cuda_fp16.h>
#include <math.h>
#include <stdint.h>

#define N_NODES 4096
#define N_EDGES 16384
#define D_IN    128
#define HID     1024

// ---------------- scratch (device globals; no allocation allowed) ----------
__device__ float g_eH[N_NODES * D_IN];
__device__ float g_Ho[N_NODES * D_IN];
__device__ float g_Hi[N_NODES * D_IN];
__device__ int   g_src[N_EDGES];
__device__ int   g_dst[N_EDGES];
__device__ float g_h4[N_NODES * (HID / 4)];
// activations as single fp16 (round-to-nearest)
__device__ __half g_x [N_NODES * 3 * D_IN];
__device__ __half g_h1[N_NODES * HID];
__device__ __half g_h2[N_NODES * HID];
__device__ __half g_h3[N_NODES * (HID / 2)];
// transposed + fp16 hi/lo split weights: [N,K] row-major
__device__ __half g_W1hi[HID * 3 * D_IN],    g_W1lo[HID * 3 * D_IN];
__device__ __half g_W2hi[HID * HID],         g_W2lo[HID * HID];
__device__ __half g_W3hi[(HID/2) * HID],     g_W3lo[(HID/2) * HID];
__device__ __half g_W4hi[(HID/4) * (HID/2)], g_W4lo[(HID/4) * (HID/2)];

// ---------------- kernel 1: eH = e*H, zero Ho/Hi ---------------------------
__global__ void k_prep(const float* __restrict__ H, const float* __restrict__ e) {
    int idx = blockIdx.x * blockDim.x + threadIdx.x;
    const int total4 = N_NODES * D_IN / 4;
    if (idx >= total4) return;
    int node = idx / (D_IN / 4);
    float ev = e[node];
    float4 h = ((const float4*)H)[idx];
    ((float4*)g_eH)[idx] = make_float4(ev * h.x, ev * h.y, ev * h.z, ev * h.w);
    float4 z = make_float4(0.f, 0.f, 0.f, 0.f);
    ((float4*)g_Ho)[idx] = z;
    ((float4*)g_Hi)[idx] = z;
}

// ---------------- kernel 2: one-hot -> index, with early exit ---------------
__global__ void k_extract(const float* __restrict__ Ro, const float* __restrict__ Ri) {
    __shared__ int found;
    int e = blockIdx.x;
    const float* row = (blockIdx.y == 0 ? Ro : Ri) + (size_t)e * N_NODES;
    int* out = (blockIdx.y == 0 ? g_src : g_dst);
    if (threadIdx.x == 0) found = 0;
    __syncthreads();
    int t = threadIdx.x;
    #pragma unroll 1
    for (int i = 0; i < 8; i++) {
        int v4 = t + i * 128;
        float4 v = ((const float4*)row)[v4];
        if (v.x != 0.f || v.y != 0.f || v.z != 0.f || v.w != 0.f) {
            int base = v4 * 4;
            int col = (v.x != 0.f) ? base : (v.y != 0.f) ? base + 1
                    : (v.z != 0.f) ? base + 2 : base + 3;
            out[e] = col;
            found = 1;
        }
        __syncthreads();
        if (found) return;
    }
}

// ---------------- kernel 3: edge scatter ------------------------------------
__global__ void k_scatter() {
    int gtid = blockIdx.x * blockDim.x + threadIdx.x;
    int warp = gtid >> 5;
    int lane = gtid & 31;
    if (warp >= N_EDGES) return;
    int s = g_src[warp];
    int d = g_dst[warp];
    float4 vs = ((const float4*)(g_eH + (size_t)s * D_IN))[lane];
    float4 vd = ((const float4*)(g_eH + (size_t)d * D_IN))[lane];
    float* ho = g_Ho + (size_t)d * D_IN + lane * 4;
    float* hi = g_Hi + (size_t)s * D_IN + lane * 4;
    atomicAdd(ho + 0, vs.x); atomicAdd(ho + 1, vs.y);
    atomicAdd(ho + 2, vs.z); atomicAdd(ho + 3, vs.w);
    atomicAdd(hi + 0, vd.x); atomicAdd(hi + 1, vd.y);
    atomicAdd(hi + 2, vd.z); atomicAdd(hi + 3, vd.w);
}

// ---------------- kernel 4: x = concat(Ho, H, Hi) -> fp16 --------------------
__global__ void k_concat(const float* __restrict__ H) {
    int idx = blockIdx.x * blockDim.x + threadIdx.x;
    const int per_row4 = 3 * D_IN / 4;
    const int total4 = N_NODES * per_row4;
    if (idx >= total4) return;
    int node = idx / per_row4;
    int c4 = idx - node * per_row4;
    float4 v;
    if (c4 < 32)       v = ((const float4*)(g_Ho + (size_t)node * D_IN))[c4];
    else if (c4 < 64)  v = ((const float4*)(H    + (size_t)node * D_IN))[c4 - 32];
    else               v = ((const float4*)(g_Hi + (size_t)node * D_IN))[c4 - 64];
    __half2 p01 = __floats2half2_rn(v.x, v.y);
    __half2 p23 = __floats2half2_rn(v.z, v.w);
    size_t off = (size_t)node * (3 * D_IN) + c4 * 4;
    *(uint2*)(g_x + off) = make_uint2(*(uint32_t*)&p01, *(uint32_t*)&p23);
}

// ---------------- fused weight transpose + fp16 hi/lo split ------------------
// W [K,N] fp32 row-major -> hi/lo [N,K] fp16 row-major; all 4 weights, 1 launch
__device__ __forceinline__ void wsplit_tile(const float* __restrict__ W,
                                            __half* __restrict__ hi, __half* __restrict__ lo,
                                            int K, int N, int bx, int by,
                                            int x, int y, float t[32][33]) {
    #pragma unroll
    for (int j = 0; j < 32; j += 8)
        t[y + j][x] = W[(size_t)(by + y + j) * N + bx + x];
    __syncthreads();
    #pragma unroll
    for (int j = 0; j < 32; j += 8) {
        int n = bx + y + j, k = by + x;
        float v = t[x][y + j];
        __half h = __float2half_rn(v);
        hi[(size_t)n * K + k] = h;
        lo[(size_t)n * K + k] = __float2half_rn(v - __half2float(h));
    }
}

__global__ void k_wsplit_all(const float* __restrict__ W1, const float* __restrict__ W2,
                             const float* __restrict__ W3, const float* __restrict__ W4,
                             __half* w1h, __half* w1l, __half* w2h, __half* w2l,
                             __half* w3h, __half* w3l, __half* w4h, __half* w4l) {
    __shared__ float t[32][33];
    int b = blockIdx.x;
    int x = threadIdx.x, y = threadIdx.y;
    // W1: 32x12=384, W2: 32x32=1024, W3: 16x32=512, W4: 8x16=128
    if (b < 384) {
        wsplit_tile(W1, w1h, w1l, 3 * D_IN, HID, (b % 32) * 32, (b / 32) * 32, x, y, t);
    } else if (b < 1408) {
        b -= 384;
        wsplit_tile(W2, w2h, w2l, HID, HID, (b % 32) * 32, (b / 32) * 32, x, y, t);
    } else if (b < 1920) {
        b -= 1408;
        wsplit_tile(W3, w3h, w3l, HID, HID / 2, (b % 16) * 32, (b / 16) * 32, x, y, t);
    } else {
        b -= 1920;
        wsplit_tile(W4, w4h, w4l, HID / 2, HID / 4, (b % 8) * 32, (b / 8) * 32, x, y, t);
    }
}

// ---------------- pipelined mma.sync GEMM (fp16, B split hi/lo) --------------
// A [M,K] fp16; B = Bhi/Blo [N,K] fp16. CTA 128x128, K-chunk 64, 3-stage
// cp.async pipeline, XOR-swizzled 128B rows. acc += A*Bhi + A*Blo (fp32).
#define TILE_B 16384
#define STAGE_B (3 * TILE_B)
#define GEMM_SMEM (3 * STAGE_B)
#define OFF_A 0
#define OFF_BHI TILE_B
#define OFF_BLO (2 * TILE_B)

__device__ __forceinline__ uint32_t smem_u32(const void* p) {
    uint32_t a;
    asm("{ .reg .u64 t; cvta.to.shared.u64 t, %1; cvt.u32.u64 %0, t; }" : "=r"(a) : "l"(p));
    return a;
}
#define SWZ(row, kg) (((row) << 7) + ((((kg) ^ ((row) & 7))) << 4))
#define CP_ASYNC16(dst, src) \
    asm volatile("cp.async.cg.shared.global [%0], [%1], 16;" :: "r"(dst), "l"(src))
#define CP_COMMIT() asm volatile("cp.async.commit_group;" ::: "memory")
#define CP_WAIT2()  asm volatile("cp.async.wait_group 2;" ::: "memory")
#define LDSM_X4(r0, r1, r2, r3, addr) \
    asm volatile("ldmatrix.sync.aligned.m8n8.x4.shared.b16 {%0,%1,%2,%3}, [%4];" \
                 : "=r"(r0), "=r"(r1), "=r"(r2), "=r"(r3) : "r"(addr))

__device__ __forceinline__ void mma_f16(float* c, const uint32_t* a, const uint32_t* b) {
    asm volatile(
        "mma.sync.aligned.m16n8k16.row.col.f32.f16.f16.f32 "
        "{%0,%1,%2,%3}, {%4,%5,%6,%7}, {%8,%9}, {%0,%1,%2,%3};"
        : "+f"(c[0]), "+f"(c[1]), "+f"(c[2]), "+f"(c[3])
        : "r"(a[0]), "r"(a[1]), "r"(a[2]), "r"(a[3]), "r"(b[0]), "r"(b[1]));
}

template <bool HALF_OUT>
__global__ void __launch_bounds__(256, 1)
k_gemm(const __half* __restrict__ A, const __half* __restrict__ Bhi,
       const __half* __restrict__ Blo, const float* __restrict__ bias,
       __half* __restrict__ Ch, float* __restrict__ Cf, int N, int K) {
    extern __shared__ char smem[];
    const uint32_t sb = smem_u32(smem);
    const int tid = threadIdx.x;
    const int wid = tid >> 5;
    const int lane = tid & 31;
    const int wm = wid & 3;
    const int wn = wid >> 2;
    const int bm0 = blockIdx.y * 128;
    const int bn0 = blockIdx.x * 128;
    const int nch = K >> 6;

    float acc[2][8][4];
    #pragma unroll
    for (int mt = 0; mt < 2; mt++)
        #pragma unroll
        for (int j = 0; j < 8; j++)
            #pragma unroll
            for (int q = 0; q < 4; q++) acc[mt][j][q] = 0.f;

    int l_row[4], l_kg[4];
    #pragma unroll
    for (int i = 0; i < 4; i++) {
        int idx = tid + i * 256;
        l_row[i] = idx >> 3;
        l_kg[i] = idx & 7;
    }

    auto issue = [&](int c, int buf) {
        uint32_t base = sb + buf * STAGE_B;
        int k0 = c << 6;
        #pragma unroll
        for (int i = 0; i < 4; i++) {
            int row = l_row[i], kg = l_kg[i];
            uint32_t d = base + SWZ(row, kg);
            size_t ka = (size_t)(bm0 + row) * K + k0 + kg * 8;
            size_t kb = (size_t)(bn0 + row) * K + k0 + kg * 8;
            CP_ASYNC16(d + OFF_A,   A   + ka);
            CP_ASYNC16(d + OFF_BHI, Bhi + kb);
            CP_ASYNC16(d + OFF_BLO, Blo + kb);
        }
    };

    issue(0, 0); CP_COMMIT();
    issue(1, 1); CP_COMMIT();

    const int a_row = wm * 32 + (lane & 15);
    const int a_kg  = lane >> 4;
    const int b_row = wn * 64 + (lane & 7) + (lane >> 4) * 8;
    const int b_kg  = (lane >> 3) & 1;

    int buf = 0;
    for (int i = 0; i < nch; i++) {
        int c = i + 2;
        if (c < nch) issue(c, c % 3);
        CP_COMMIT();
        CP_WAIT2();
        __syncthreads();

        uint32_t sbase = sb + buf * STAGE_B;
        #pragma unroll
        for (int ks8 = 0; ks8 < 8; ks8 += 2) {
            uint32_t af[2][4], bhi[8][2], blo[8][2];
            #pragma unroll
            for (int mt = 0; mt < 2; mt++) {
                uint32_t ad = sbase + OFF_A + SWZ(a_row + mt * 16, a_kg + ks8);
                LDSM_X4(af[mt][0], af[mt][1], af[mt][2], af[mt][3], ad);
            }
            #pragma unroll
            for (int jp = 0; jp < 4; jp++) {
                uint32_t bd = sbase + OFF_BHI + SWZ(b_row + jp * 16, b_kg + ks8);
                LDSM_X4(bhi[jp*2][0], bhi[jp*2][1], bhi[jp*2+1][0], bhi[jp*2+1][1], bd);
                LDSM_X4(blo[jp*2][0], blo[jp*2][1], blo[jp*2+1][0], blo[jp*2+1][1], bd + TILE_B);
            }
            #pragma unroll
            for (int mt = 0; mt < 2; mt++)
                #pragma unroll
                for (int j = 0; j < 8; j++) {
                    mma_f16(acc[mt][j], af[mt], bhi[j]);
                    mma_f16(acc[mt][j], af[mt], blo[j]);
                }
        }
        __syncthreads();
        buf = (buf == 2) ? 0 : buf + 1;
    }

    // ---- epilogue: bias + tanh ----
    const int g = lane >> 2, tig = lane & 3;
    #pragma unroll
    for (int mt = 0; mt < 2; mt++) {
        int row0 = bm0 + wm * 32 + mt * 16 + g;
        #pragma unroll
        for (int j = 0; j < 8; j++) {
            int col = bn0 + wn * 64 + j * 8 + tig * 2;
            float bc0 = __ldg(bias + col), bc1 = __ldg(bias + col + 1);
            float v00 = tanhf(acc[mt][j][0] + bc0);
            float v01 = tanhf(acc[mt][j][1] + bc1);
            float v10 = tanhf(acc[mt][j][2] + bc0);
            float v11 = tanhf(acc[mt][j][3] + bc1);
            if (HALF_OUT) {
                __half2 p0 = __floats2half2_rn(v00, v01);
                __half2 p1 = __floats2half2_rn(v10, v11);
                *(uint32_t*)(Ch + (size_t)row0 * N + col)       = *(uint32_t*)&p0;
                *(uint32_t*)(Ch + (size_t)(row0 + 8) * N + col) = *(uint32_t*)&p1;
            } else {
                *(float2*)(Cf + (size_t)row0 * N + col)       = make_float2(v00, v01);
                *(float2*)(Cf + (size_t)(row0 + 8) * N + col) = make_float2(v10, v11);
            }
        }
    }
}

// ---------------- final layer: sigmoid(h4 @ W5 + b5), N=1 -------------------
__global__ void k_final(const float* __restrict__ h4, const float* __restrict__ W5,
                        const float* __restrict__ b5, float* __restrict__ out) {
    int gtid = blockIdx.x * blockDim.x + threadIdx.x;
    int row = gtid >> 5;
    int lane = gtid & 31;
    if (row >= N_NODES) return;
    const float4* a = (const float4*)(h4 + (size_t)row * (HID / 4));
    const float4* w = (const float4*)W5;
    float s = 0.f;
    #pragma unroll
    for (int i = 0; i < 2; i++) {
        int v4 = lane + i * 32;
        float4 x = a[v4], y = w[v4];
        s += x.x * y.x + x.y * y.y + x.z * y.z + x.w * y.w;
    }
    #pragma unroll
    for (int o = 16; o; o >>= 1) s += __shfl_xor_sync(0xffffffffu, s, o);
    if (lane == 0) out[row] = 1.f / (1.f + expf(-(s + b5[0])));
}

// ---------------- launcher ---------------------------------------------------
extern "C" void kernel_launch(void* const* d_in, const int* in_sizes, int n_in,
                              void* d_out, int out_size) {
    const float* H  = (const float*)d_in[0];
    const float* Ro = (const float*)d_in[1];
    const float* Ri = (const float*)d_in[2];
    const float* e  = (const float*)d_in[3];
    const float* W1 = (const float*)d_in[4];   const float* b1 = (const float*)d_in[5];
    const float* W2 = (const float*)d_in[6];   const float* b2 = (const float*)d_in[7];
    const float* W3 = (const float*)d_in[8];   const float* b3 = (const float*)d_in[9];
    const float* W4 = (const float*)d_in[10];  const float* b4 = (const float*)d_in[11];
    const float* W5 = (const float*)d_in[12];  const float* b5 = (const float*)d_in[13];
    float* out = (float*)d_out;
    (void)in_sizes; (void)n_in; (void)out_size;

    __half *xp, *h1p, *h2p, *h3p;
    __half *w1h, *w1l, *w2h, *w2l, *w3h, *w3l, *w4h, *w4l;
    float* p_h4;
    cudaGetSymbolAddress((void**)&xp,  g_x);
    cudaGetSymbolAddress((void**)&h1p, g_h1);
    cudaGetSymbolAddress((void**)&h2p, g_h2);
    cudaGetSymbolAddress((void**)&h3p, g_h3);
    cudaGetSymbolAddress((void**)&p_h4, g_h4);
    cudaGetSymbolAddress((void**)&w1h, g_W1hi); cudaGetSymbolAddress((void**)&w1l, g_W1lo);
    cudaGetSymbolAddress((void**)&w2h, g_W2hi); cudaGetSymbolAddress((void**)&w2l, g_W2lo);
    cudaGetSymbolAddress((void**)&w3h, g_W3hi); cudaGetSymbolAddress((void**)&w3l, g_W3lo);
    cudaGetSymbolAddress((void**)&w4h, g_W4hi); cudaGetSymbolAddress((void**)&w4l, g_W4lo);

    cudaFuncSetAttribute(k_gemm<true>,  cudaFuncAttributeMaxDynamicSharedMemorySize, GEMM_SMEM);
    cudaFuncSetAttribute(k_gemm<false>, cudaFuncAttributeMaxDynamicSharedMemorySize, GEMM_SMEM);

    // front-end
    k_prep<<<(N_NODES * D_IN / 4 + 255) / 256, 256>>>(H, e);
    k_wsplit_all<<<2048, dim3(32, 8)>>>(W1, W2, W3, W4, w1h, w1l, w2h, w2l,
                                        w3h, w3l, w4h, w4l);
    k_extract<<<dim3(N_EDGES, 2), 128>>>(Ro, Ri);
    k_scatter<<<(N_EDGES * 32 + 255) / 256, 256>>>();
    k_concat<<<(N_NODES * 96 + 255) / 256, 256>>>(H);
    // MLP (fp16 A x fp16 hi/lo B, 2 MMA terms, cp.async pipelined)
    k_gemm<true><<<dim3(HID / 128,     N_NODES / 128), 256, GEMM_SMEM>>>(xp,  w1h, w1l, b1, h1p, nullptr, HID,     3 * D_IN);
    k_gemm<true><<<dim3(HID / 128,     N_NODES / 128), 256, GEMM_SMEM>>>(h1p, w2h, w2l, b2, h2p, nullptr, HID,     HID);
    k_gemm<true><<<dim3(HID / 2 / 128, N_NODES / 128), 256, GEMM_SMEM>>>(h2p, w3h, w3l, b3, h3p, nullptr, HID / 2, HID);
    k_gemm<false><<<dim3(HID / 4 / 128, N_NODES / 128), 256, GEMM_SMEM>>>(h3p, w4h, w4l, b4, nullptr, p_h4, HID / 4, HID / 2);
    // head
    k_final<<<(N_NODES * 32 + 255) / 256, 256>>>(p_h4, W5, b5, out);
}

// round 6
// speedup vs baseline: 3.9952x; 1.2929x over previous
#include <cuda_runtime.h>
#include <cuda_fp16.h>
#include <math.h>
#include <stdint.h>

#define N_NODES 4096
#define N_EDGES 16384
#define D_IN    128
#define HID     1024

// ---------------- scratch (device globals; no allocation allowed) ----------
__device__ float g_eH[N_NODES * D_IN];
__device__ float g_Ho[N_NODES * D_IN];
__device__ float g_Hi[N_NODES * D_IN];
__device__ int   g_src[N_EDGES];
__device__ int   g_dst[N_EDGES];
__device__ float g_h4[N_NODES * (HID / 4)];
// activations as single fp16 (round-to-nearest)
__device__ __half g_x [N_NODES * 3 * D_IN];
__device__ __half g_h1[N_NODES * HID];
__device__ __half g_h2[N_NODES * HID];
__device__ __half g_h3[N_NODES * (HID / 2)];
// transposed fp16 weights: [N,K] row-major
__device__ __half g_W1[HID * 3 * D_IN];
__device__ __half g_W2[HID * HID];
__device__ __half g_W3[(HID/2) * HID];
__device__ __half g_W4[(HID/4) * (HID/2)];

// ---------------- kernel 1: eH = e*H, zero Ho/Hi ---------------------------
__global__ void k_prep(const float* __restrict__ H, const float* __restrict__ e) {
    int idx = blockIdx.x * blockDim.x + threadIdx.x;
    const int total4 = N_NODES * D_IN / 4;
    if (idx >= total4) return;
    int node = idx / (D_IN / 4);
    float ev = e[node];
    float4 h = ((const float4*)H)[idx];
    ((float4*)g_eH)[idx] = make_float4(ev * h.x, ev * h.y, ev * h.z, ev * h.w);
    float4 z = make_float4(0.f, 0.f, 0.f, 0.f);
    ((float4*)g_Ho)[idx] = z;
    ((float4*)g_Hi)[idx] = z;
}

// ---------------- kernel 2: one-hot -> index, with early exit ---------------
__global__ void k_extract(const float* __restrict__ Ro, const float* __restrict__ Ri) {
    __shared__ int found;
    int e = blockIdx.x;
    const float* row = (blockIdx.y == 0 ? Ro : Ri) + (size_t)e * N_NODES;
    int* out = (blockIdx.y == 0 ? g_src : g_dst);
    if (threadIdx.x == 0) found = 0;
    __syncthreads();
    int t = threadIdx.x;
    #pragma unroll 1
    for (int i = 0; i < 8; i++) {
        int v4 = t + i * 128;
        float4 v = ((const float4*)row)[v4];
        if (v.x != 0.f || v.y != 0.f || v.z != 0.f || v.w != 0.f) {
            int base = v4 * 4;
            int col = (v.x != 0.f) ? base : (v.y != 0.f) ? base + 1
                    : (v.z != 0.f) ? base + 2 : base + 3;
            out[e] = col;
            found = 1;
        }
        __syncthreads();
        if (found) return;
    }
}

// ---------------- kernel 3: edge scatter ------------------------------------
__global__ void k_scatter() {
    int gtid = blockIdx.x * blockDim.x + threadIdx.x;
    int warp = gtid >> 5;
    int lane = gtid & 31;
    if (warp >= N_EDGES) return;
    int s = g_src[warp];
    int d = g_dst[warp];
    float4 vs = ((const float4*)(g_eH + (size_t)s * D_IN))[lane];
    float4 vd = ((const float4*)(g_eH + (size_t)d * D_IN))[lane];
    float* ho = g_Ho + (size_t)d * D_IN + lane * 4;
    float* hi = g_Hi + (size_t)s * D_IN + lane * 4;
    atomicAdd(ho + 0, vs.x); atomicAdd(ho + 1, vs.y);
    atomicAdd(ho + 2, vs.z); atomicAdd(ho + 3, vs.w);
    atomicAdd(hi + 0, vd.x); atomicAdd(hi + 1, vd.y);
    atomicAdd(hi + 2, vd.z); atomicAdd(hi + 3, vd.w);
}

// ---------------- kernel 4: x = concat(Ho, H, Hi) -> fp16 --------------------
__global__ void k_concat(const float* __restrict__ H) {
    int idx = blockIdx.x * blockDim.x + threadIdx.x;
    const int per_row4 = 3 * D_IN / 4;
    const int total4 = N_NODES * per_row4;
    if (idx >= total4) return;
    int node = idx / per_row4;
    int c4 = idx - node * per_row4;
    float4 v;
    if (c4 < 32)       v = ((const float4*)(g_Ho + (size_t)node * D_IN))[c4];
    else if (c4 < 64)  v = ((const float4*)(H    + (size_t)node * D_IN))[c4 - 32];
    else               v = ((const float4*)(g_Hi + (size_t)node * D_IN))[c4 - 64];
    __half2 p01 = __floats2half2_rn(v.x, v.y);
    __half2 p23 = __floats2half2_rn(v.z, v.w);
    size_t off = (size_t)node * (3 * D_IN) + c4 * 4;
    *(uint2*)(g_x + off) = make_uint2(*(uint32_t*)&p01, *(uint32_t*)&p23);
}

// ---------------- fused weight transpose + fp16 convert ----------------------
// W [K,N] fp32 row-major -> [N,K] fp16 row-major; all 4 weights, 1 launch
__device__ __forceinline__ void wconv_tile(const float* __restrict__ W,
                                           __half* __restrict__ O,
                                           int K, int N, int bx, int by,
                                           int x, int y, float t[32][33]) {
    #pragma unroll
    for (int j = 0; j < 32; j += 8)
        t[y + j][x] = W[(size_t)(by + y + j) * N + bx + x];
    __syncthreads();
    #pragma unroll
    for (int j = 0; j < 32; j += 8) {
        int n = bx + y + j, k = by + x;
        O[(size_t)n * K + k] = __float2half_rn(t[x][y + j]);
    }
}

__global__ void k_wconv_all(const float* __restrict__ W1, const float* __restrict__ W2,
                            const float* __restrict__ W3, const float* __restrict__ W4,
                            __half* w1, __half* w2, __half* w3, __half* w4) {
    __shared__ float t[32][33];
    int b = blockIdx.x;
    int x = threadIdx.x, y = threadIdx.y;
    // W1: 32x12=384, W2: 32x32=1024, W3: 16x32=512, W4: 8x16=128
    if (b < 384) {
        wconv_tile(W1, w1, 3 * D_IN, HID, (b % 32) * 32, (b / 32) * 32, x, y, t);
    } else if (b < 1408) {
        b -= 384;
        wconv_tile(W2, w2, HID, HID, (b % 32) * 32, (b / 32) * 32, x, y, t);
    } else if (b < 1920) {
        b -= 1408;
        wconv_tile(W3, w3, HID, HID / 2, (b % 16) * 32, (b / 16) * 32, x, y, t);
    } else {
        b -= 1920;
        wconv_tile(W4, w4, HID / 2, HID / 4, (b % 8) * 32, (b / 8) * 32, x, y, t);
    }
}

// ---------------- pipelined mma.sync GEMM (pure fp16) ------------------------
// A [M,K] fp16; B [N,K] fp16. CTA 128x128, K-chunk 64, 3-stage cp.async
// pipeline, XOR-swizzled 128B rows, fp32 accumulate. 2 CTAs/SM (96KB smem).
#define TILE_B 16384
#define STAGE_B (2 * TILE_B)
#define GEMM_SMEM (3 * STAGE_B)
#define OFF_A 0
#define OFF_B TILE_B

__device__ __forceinline__ uint32_t smem_u32(const void* p) {
    uint32_t a;
    asm("{ .reg .u64 t; cvta.to.shared.u64 t, %1; cvt.u32.u64 %0, t; }" : "=r"(a) : "l"(p));
    return a;
}
#define SWZ(row, kg) (((row) << 7) + ((((kg) ^ ((row) & 7))) << 4))
#define CP_ASYNC16(dst, src) \
    asm volatile("cp.async.cg.shared.global [%0], [%1], 16;" :: "r"(dst), "l"(src))
#define CP_COMMIT() asm volatile("cp.async.commit_group;" ::: "memory")
#define CP_WAIT2()  asm volatile("cp.async.wait_group 2;" ::: "memory")
#define LDSM_X4(r0, r1, r2, r3, addr) \
    asm volatile("ldmatrix.sync.aligned.m8n8.x4.shared.b16 {%0,%1,%2,%3}, [%4];" \
                 : "=r"(r0), "=r"(r1), "=r"(r2), "=r"(r3) : "r"(addr))

__device__ __forceinline__ void mma_f16(float* c, const uint32_t* a, const uint32_t* b) {
    asm volatile(
        "mma.sync.aligned.m16n8k16.row.col.f32.f16.f16.f32 "
        "{%0,%1,%2,%3}, {%4,%5,%6,%7}, {%8,%9}, {%0,%1,%2,%3};"
        : "+f"(c[0]), "+f"(c[1]), "+f"(c[2]), "+f"(c[3])
        : "r"(a[0]), "r"(a[1]), "r"(a[2]), "r"(a[3]), "r"(b[0]), "r"(b[1]));
}

template <bool HALF_OUT>
__global__ void __launch_bounds__(256, 2)
k_gemm(const __half* __restrict__ A, const __half* __restrict__ B,
       const float* __restrict__ bias,
       __half* __restrict__ Ch, float* __restrict__ Cf, int N, int K) {
    extern __shared__ char smem[];
    const uint32_t sb = smem_u32(smem);
    const int tid = threadIdx.x;
    const int wid = tid >> 5;
    const int lane = tid & 31;
    const int wm = wid & 3;
    const int wn = wid >> 2;
    const int bm0 = blockIdx.y * 128;
    const int bn0 = blockIdx.x * 128;
    const int nch = K >> 6;

    float acc[2][8][4];
    #pragma unroll
    for (int mt = 0; mt < 2; mt++)
        #pragma unroll
        for (int j = 0; j < 8; j++)
            #pragma unroll
            for (int q = 0; q < 4; q++) acc[mt][j][q] = 0.f;

    int l_row[4], l_kg[4];
    #pragma unroll
    for (int i = 0; i < 4; i++) {
        int idx = tid + i * 256;
        l_row[i] = idx >> 3;
        l_kg[i] = idx & 7;
    }

    auto issue = [&](int c, int buf) {
        uint32_t base = sb + buf * STAGE_B;
        int k0 = c << 6;
        #pragma unroll
        for (int i = 0; i < 4; i++) {
            int row = l_row[i], kg = l_kg[i];
            uint32_t d = base + SWZ(row, kg);
            size_t ka = (size_t)(bm0 + row) * K + k0 + kg * 8;
            size_t kb = (size_t)(bn0 + row) * K + k0 + kg * 8;
            CP_ASYNC16(d + OFF_A, A + ka);
            CP_ASYNC16(d + OFF_B, B + kb);
        }
    };

    issue(0, 0); CP_COMMIT();
    issue(1, 1); CP_COMMIT();

    const int a_row = wm * 32 + (lane & 15);
    const int a_kg  = lane >> 4;
    const int b_row = wn * 64 + (lane & 7) + (lane >> 4) * 8;
    const int b_kg  = (lane >> 3) & 1;

    int buf = 0;
    for (int i = 0; i < nch; i++) {
        int c = i + 2;
        if (c < nch) issue(c, c % 3);
        CP_COMMIT();
        CP_WAIT2();
        __syncthreads();

        uint32_t sbase = sb + buf * STAGE_B;
        #pragma unroll
        for (int ks8 = 0; ks8 < 8; ks8 += 2) {
            uint32_t af[2][4], bf[8][2];
            #pragma unroll
            for (int mt = 0; mt < 2; mt++) {
                uint32_t ad = sbase + OFF_A + SWZ(a_row + mt * 16, a_kg + ks8);
                LDSM_X4(af[mt][0], af[mt][1], af[mt][2], af[mt][3], ad);
            }
            #pragma unroll
            for (int jp = 0; jp < 4; jp++) {
                uint32_t bd = sbase + OFF_B + SWZ(b_row + jp * 16, b_kg + ks8);
                LDSM_X4(bf[jp*2][0], bf[jp*2][1], bf[jp*2+1][0], bf[jp*2+1][1], bd);
            }
            #pragma unroll
            for (int mt = 0; mt < 2; mt++)
                #pragma unroll
                for (int j = 0; j < 8; j++)
                    mma_f16(acc[mt][j], af[mt], bf[j]);
        }
        __syncthreads();
        buf = (buf == 2) ? 0 : buf + 1;
    }

    // ---- epilogue: bias + tanh ----
    const int g = lane >> 2, tig = lane & 3;
    #pragma unroll
    for (int mt = 0; mt < 2; mt++) {
        int row0 = bm0 + wm * 32 + mt * 16 + g;
        #pragma unroll
        for (int j = 0; j < 8; j++) {
            int col = bn0 + wn * 64 + j * 8 + tig * 2;
            float bc0 = __ldg(bias + col), bc1 = __ldg(bias + col + 1);
            float v00 = tanhf(acc[mt][j][0] + bc0);
            float v01 = tanhf(acc[mt][j][1] + bc1);
            float v10 = tanhf(acc[mt][j][2] + bc0);
            float v11 = tanhf(acc[mt][j][3] + bc1);
            if (HALF_OUT) {
                __half2 p0 = __floats2half2_rn(v00, v01);
                __half2 p1 = __floats2half2_rn(v10, v11);
                *(uint32_t*)(Ch + (size_t)row0 * N + col)       = *(uint32_t*)&p0;
                *(uint32_t*)(Ch + (size_t)(row0 + 8) * N + col) = *(uint32_t*)&p1;
            } else {
                *(float2*)(Cf + (size_t)row0 * N + col)       = make_float2(v00, v01);
                *(float2*)(Cf + (size_t)(row0 + 8) * N + col) = make_float2(v10, v11);
            }
        }
    }
}

// ---------------- final layer: sigmoid(h4 @ W5 + b5), N=1 -------------------
__global__ void k_final(const float* __restrict__ h4, const float* __restrict__ W5,
                        const float* __restrict__ b5, float* __restrict__ out) {
    int gtid = blockIdx.x * blockDim.x + threadIdx.x;
    int row = gtid >> 5;
    int lane = gtid & 31;
    if (row >= N_NODES) return;
    const float4* a = (const float4*)(h4 + (size_t)row * (HID / 4));
    const float4* w = (const float4*)W5;
    float s = 0.f;
    #pragma unroll
    for (int i = 0; i < 2; i++) {
        int v4 = lane + i * 32;
        float4 x = a[v4], y = w[v4];
        s += x.x * y.x + x.y * y.y + x.z * y.z + x.w * y.w;
    }
    #pragma unroll
    for (int o = 16; o; o >>= 1) s += __shfl_xor_sync(0xffffffffu, s, o);
    if (lane == 0) out[row] = 1.f / (1.f + expf(-(s + b5[0])));
}

// ---------------- launcher ---------------------------------------------------
extern "C" void kernel_launch(void* const* d_in, const int* in_sizes, int n_in,
                              void* d_out, int out_size) {
    const float* H  = (const float*)d_in[0];
    const float* Ro = (const float*)d_in[1];
    const float* Ri = (const float*)d_in[2];
    const float* e  = (const float*)d_in[3];
    const float* W1 = (const float*)d_in[4];   const float* b1 = (const float*)d_in[5];
    const float* W2 = (const float*)d_in[6];   const float* b2 = (const float*)d_in[7];
    const float* W3 = (const float*)d_in[8];   const float* b3 = (const float*)d_in[9];
    const float* W4 = (const float*)d_in[10];  const float* b4 = (const float*)d_in[11];
    const float* W5 = (const float*)d_in[12];  const float* b5 = (const float*)d_in[13];
    float* out = (float*)d_out;
    (void)in_sizes; (void)n_in; (void)out_size;

    __half *xp, *h1p, *h2p, *h3p, *w1, *w2, *w3, *w4;
    float* p_h4;
    cudaGetSymbolAddress((void**)&xp,  g_x);
    cudaGetSymbolAddress((void**)&h1p, g_h1);
    cudaGetSymbolAddress((void**)&h2p, g_h2);
    cudaGetSymbolAddress((void**)&h3p, g_h3);
    cudaGetSymbolAddress((void**)&p_h4, g_h4);
    cudaGetSymbolAddress((void**)&w1, g_W1);
    cudaGetSymbolAddress((void**)&w2, g_W2);
    cudaGetSymbolAddress((void**)&w3, g_W3);
    cudaGetSymbolAddress((void**)&w4, g_W4);

    cudaFuncSetAttribute(k_gemm<true>,  cudaFuncAttributeMaxDynamicSharedMemorySize, GEMM_SMEM);
    cudaFuncSetAttribute(k_gemm<false>, cudaFuncAttributeMaxDynamicSharedMemorySize, GEMM_SMEM);

    // front-end
    k_prep<<<(N_NODES * D_IN / 4 + 255) / 256, 256>>>(H, e);
    k_wconv_all<<<2048, dim3(32, 8)>>>(W1, W2, W3, W4, w1, w2, w3, w4);
    k_extract<<<dim3(N_EDGES, 2), 128>>>(Ro, Ri);
    k_scatter<<<(N_EDGES * 32 + 255) / 256, 256>>>();
    k_concat<<<(N_NODES * 96 + 255) / 256, 256>>>(H);
    // MLP (pure fp16 MMA, fp32 accumulate, cp.async pipelined, 2 CTA/SM)
    k_gemm<true><<<dim3(HID / 128,     N_NODES / 128), 256, GEMM_SMEM>>>(xp,  w1, b1, h1p, nullptr, HID,     3 * D_IN);
    k_gemm<true><<<dim3(HID / 128,     N_NODES / 128), 256, GEMM_SMEM>>>(h1p, w2, b2, h2p, nullptr, HID,     HID);
    k_gemm<true><<<dim3(HID / 2 / 128, N_NODES / 128), 256, GEMM_SMEM>>>(h2p, w3, b3, h3p, nullptr, HID / 2, HID);
    k_gemm<false><<<dim3(HID / 4 / 128, N_NODES / 128), 256, GEMM_SMEM>>>(h3p, w4, b4, nullptr, p_h4, HID / 4, HID / 2);
    // head
    k_final<<<(N_NODES * 32 + 255) / 256, 256>>>(p_h4, W5, b5, out);
}

// round 10
// speedup vs baseline: 4.2354x; 1.0601x over previous
#include <cuda_runtime.h>
#include <cuda_fp16.h>
#include <math.h>
#include <stdint.h>

#define N_NODES 4096
#define N_EDGES 16384
#define D_IN    128
#define HID     1024

// ---------------- scratch (device globals; no allocation allowed) ----------
__device__ float g_eH[N_NODES * D_IN];
__device__ float g_Ho[N_NODES * D_IN];
__device__ float g_Hi[N_NODES * D_IN];
__device__ int   g_src[N_EDGES];
__device__ int   g_dst[N_EDGES];
__device__ float g_h4[N_NODES * (HID / 4)];
// activations as single fp16 (round-to-nearest)
__device__ __half g_x [N_NODES * 3 * D_IN];
__device__ __half g_h1[N_NODES * HID];
__device__ __half g_h2[N_NODES * HID];
__device__ __half g_h3[N_NODES * (HID / 2)];
// transposed fp16 weights: [N,K] row-major
__device__ __half g_W1[HID * 3 * D_IN];
__device__ __half g_W2[HID * HID];
__device__ __half g_W3[(HID/2) * HID];
__device__ __half g_W4[(HID/4) * (HID/2)];

// ---------------- kernel 1: eH = e*H, zero Ho/Hi ---------------------------
__global__ void k_prep(const float* __restrict__ H, const float* __restrict__ e) {
    int idx = blockIdx.x * blockDim.x + threadIdx.x;
    const int total4 = N_NODES * D_IN / 4;
    if (idx >= total4) return;
    int node = idx / (D_IN / 4);
    float ev = e[node];
    float4 h = ((const float4*)H)[idx];
    ((float4*)g_eH)[idx] = make_float4(ev * h.x, ev * h.y, ev * h.z, ev * h.w);
    float4 z = make_float4(0.f, 0.f, 0.f, 0.f);
    ((float4*)g_Ho)[idx] = z;
    ((float4*)g_Hi)[idx] = z;
}

// ---------------- kernel 2: one-hot -> index, with early exit ---------------
__global__ void k_extract(const float* __restrict__ Ro, const float* __restrict__ Ri) {
    __shared__ int found;
    int e = blockIdx.x;
    const float* row = (blockIdx.y == 0 ? Ro : Ri) + (size_t)e * N_NODES;
    int* out = (blockIdx.y == 0 ? g_src : g_dst);
    if (threadIdx.x == 0) found = 0;
    __syncthreads();
    int t = threadIdx.x;
    #pragma unroll 1
    for (int i = 0; i < 8; i++) {
        int v4 = t + i * 128;
        float4 v = ((const float4*)row)[v4];
        if (v.x != 0.f || v.y != 0.f || v.z != 0.f || v.w != 0.f) {
            int base = v4 * 4;
            int col = (v.x != 0.f) ? base : (v.y != 0.f) ? base + 1
                    : (v.z != 0.f) ? base + 2 : base + 3;
            out[e] = col;
            found = 1;
        }
        __syncthreads();
        if (found) return;
    }
}

// ---------------- kernel 3: edge scatter (vector reductions) -----------------
#define REDV4(ptr, v) \
    asm volatile("red.global.add.v4.f32 [%0], {%1,%2,%3,%4};" \
                 :: "l"(ptr), "f"((v).x), "f"((v).y), "f"((v).z), "f"((v).w) : "memory")

__global__ void k_scatter() {
    int gtid = blockIdx.x * blockDim.x + threadIdx.x;
    int warp = gtid >> 5;
    int lane = gtid & 31;
    if (warp >= N_EDGES) return;
    int s = g_src[warp];
    int d = g_dst[warp];
    float4 vs = ((const float4*)(g_eH + (size_t)s * D_IN))[lane];
    float4 vd = ((const float4*)(g_eH + (size_t)d * D_IN))[lane];
    float* ho = g_Ho + (size_t)d * D_IN + lane * 4;  // Ho[dst] += eH[src]
    float* hi = g_Hi + (size_t)s * D_IN + lane * 4;  // Hi[src] += eH[dst]
    REDV4(ho, vs);
    REDV4(hi, vd);
}

// ---------------- kernel 4: x = concat(Ho, H, Hi) -> fp16 --------------------
__global__ void k_concat(const float* __restrict__ H) {
    int idx = blockIdx.x * blockDim.x + threadIdx.x;
    const int per_row4 = 3 * D_IN / 4;
    const int total4 = N_NODES * per_row4;
    if (idx >= total4) return;
    int node = idx / per_row4;
    int c4 = idx - node * per_row4;
    float4 v;
    if (c4 < 32)       v = ((const float4*)(g_Ho + (size_t)node * D_IN))[c4];
    else if (c4 < 64)  v = ((const float4*)(H    + (size_t)node * D_IN))[c4 - 32];
    else               v = ((const float4*)(g_Hi + (size_t)node * D_IN))[c4 - 64];
    __half2 p01 = __floats2half2_rn(v.x, v.y);
    __half2 p23 = __floats2half2_rn(v.z, v.w);
    size_t off = (size_t)node * (3 * D_IN) + c4 * 4;
    *(uint2*)(g_x + off) = make_uint2(*(uint32_t*)&p01, *(uint32_t*)&p23);
}

// ---------------- fused weight transpose + fp16 convert ----------------------
__device__ __forceinline__ void wconv_tile(const float* __restrict__ W,
                                           __half* __restrict__ O,
                                           int K, int N, int bx, int by,
                                           int x, int y, float t[32][33]) {
    #pragma unroll
    for (int j = 0; j < 32; j += 8)
        t[y + j][x] = W[(size_t)(by + y + j) * N + bx + x];
    __syncthreads();
    #pragma unroll
    for (int j = 0; j < 32; j += 8) {
        int n = bx + y + j, k = by + x;
        O[(size_t)n * K + k] = __float2half_rn(t[x][y + j]);
    }
}

__global__ void k_wconv_all(const float* __restrict__ W1, const float* __restrict__ W2,
                            const float* __restrict__ W3, const float* __restrict__ W4,
                            __half* w1, __half* w2, __half* w3, __half* w4) {
    __shared__ float t[32][33];
    int b = blockIdx.x;
    int x = threadIdx.x, y = threadIdx.y;
    if (b < 384) {
        wconv_tile(W1, w1, 3 * D_IN, HID, (b % 32) * 32, (b / 32) * 32, x, y, t);
    } else if (b < 1408) {
        b -= 384;
        wconv_tile(W2, w2, HID, HID, (b % 32) * 32, (b / 32) * 32, x, y, t);
    } else if (b < 1920) {
        b -= 1408;
        wconv_tile(W3, w3, HID, HID / 2, (b % 16) * 32, (b / 16) * 32, x, y, t);
    } else {
        b -= 1920;
        wconv_tile(W4, w4, HID / 2, HID / 4, (b % 8) * 32, (b / 8) * 32, x, y, t);
    }
}

// ---------------- pipelined mma.sync GEMM (pure fp16, templated BN) ----------
// A [M,K] fp16; B [N,K] fp16. CTA 128xBN, K-chunk 64, 3-stage cp.async
// pipeline, XOR-swizzled 128B rows, fp32 accumulate, 2 CTAs/SM.
#define TILE_A 16384

__device__ __forceinline__ uint32_t smem_u32(const void* p) {
    uint32_t a;
    asm("{ .reg .u64 t; cvta.to.shared.u64 t, %1; cvt.u32.u64 %0, t; }" : "=r"(a) : "l"(p));
    return a;
}
#define SWZ(row, kg) (((row) << 7) + ((((kg) ^ ((row) & 7))) << 4))
#define CP_ASYNC16(dst, src) \
    asm volatile("cp.async.cg.shared.global [%0], [%1], 16;" :: "r"(dst), "l"(src))
#define CP_COMMIT() asm volatile("cp.async.commit_group;" ::: "memory")
#define CP_WAIT2()  asm volatile("cp.async.wait_group 2;" ::: "memory")
#define LDSM_X4(r0, r1, r2, r3, addr) \
    asm volatile("ldmatrix.sync.aligned.m8n8.x4.shared.b16 {%0,%1,%2,%3}, [%4];" \
                 : "=r"(r0), "=r"(r1), "=r"(r2), "=r"(r3) : "r"(addr))

__device__ __forceinline__ void mma_f16(float* c, const uint32_t* a, const uint32_t* b) {
    asm volatile(
        "mma.sync.aligned.m16n8k16.row.col.f32.f16.f16.f32 "
        "{%0,%1,%2,%3}, {%4,%5,%6,%7}, {%8,%9}, {%0,%1,%2,%3};"
        : "+f"(c[0]), "+f"(c[1]), "+f"(c[2]), "+f"(c[3])
        : "r"(a[0]), "r"(a[1]), "r"(a[2]), "r"(a[3]), "r"(b[0]), "r"(b[1]));
}

template <int BN, bool HALF_OUT>
__global__ void __launch_bounds__(256, 2)
k_gemm(const __half* __restrict__ A, const __half* __restrict__ B,
       const float* __restrict__ bias,
       __half* __restrict__ Ch, float* __restrict__ Cf, int N, int K) {
    constexpr int TILE_BB = BN * 128;          // B tile bytes
    constexpr int STAGE_B = TILE_A + TILE_BB;  // per-stage bytes
    constexpr int OFF_B = TILE_A;
    constexpr int NJ = BN / 16;                // 8-col j tiles per n-warp
    constexpr int B_ITERS = BN / 32;           // B cp.async iterations

    extern __shared__ char smem[];
    const uint32_t sb = smem_u32(smem);
    const int tid = threadIdx.x;
    const int wid = tid >> 5;
    const int lane = tid & 31;
    const int wm = wid & 3;
    const int wn = wid >> 2;
    const int bm0 = blockIdx.y * 128;
    const int bn0 = blockIdx.x * BN;
    const int nch = K >> 6;

    float acc[2][NJ][4];
    #pragma unroll
    for (int mt = 0; mt < 2; mt++)
        #pragma unroll
        for (int j = 0; j < NJ; j++)
            #pragma unroll
            for (int q = 0; q < 4; q++) acc[mt][j][q] = 0.f;

    auto issue = [&](int c, int buf) {
        uint32_t base = sb + buf * STAGE_B;
        int k0 = c << 6;
        #pragma unroll
        for (int i = 0; i < 4; i++) {
            int idx = tid + i * 256;
            int row = idx >> 3, kg = idx & 7;
            CP_ASYNC16(base + SWZ(row, kg), A + (size_t)(bm0 + row) * K + k0 + kg * 8);
        }
        #pragma unroll
        for (int i = 0; i < B_ITERS; i++) {
            int idx = tid + i * 256;
            int row = idx >> 3, kg = idx & 7;
            CP_ASYNC16(base + OFF_B + SWZ(row, kg), B + (size_t)(bn0 + row) * K + k0 + kg * 8);
        }
    };

    issue(0, 0); CP_COMMIT();
    issue(1, 1); CP_COMMIT();

    const int a_row = wm * 32 + (lane & 15);
    const int a_kg  = lane >> 4;
    const int b_row = wn * (BN / 2) + (lane & 7) + (lane >> 4) * 8;
    const int b_kg  = (lane >> 3) & 1;

    int buf = 0;
    for (int i = 0; i < nch; i++) {
        int c = i + 2;
        if (c < nch) issue(c, c % 3);
        CP_COMMIT();
        CP_WAIT2();
        __syncthreads();

        uint32_t sbase = sb + buf * STAGE_B;
        #pragma unroll
        for (int ks8 = 0; ks8 < 8; ks8 += 2) {
            uint32_t af[2][4], bf[NJ][2];
            #pragma unroll
            for (int mt = 0; mt < 2; mt++) {
                uint32_t ad = sbase + SWZ(a_row + mt * 16, a_kg + ks8);
                LDSM_X4(af[mt][0], af[mt][1], af[mt][2], af[mt][3], ad);
            }
            #pragma unroll
            for (int jp = 0; jp < NJ / 2; jp++) {
                uint32_t bd = sbase + OFF_B + SWZ(b_row + jp * 16, b_kg + ks8);
                LDSM_X4(bf[jp*2][0], bf[jp*2][1], bf[jp*2+1][0], bf[jp*2+1][1], bd);
            }
            #pragma unroll
            for (int mt = 0; mt < 2; mt++)
                #pragma unroll
                for (int j = 0; j < NJ; j++)
                    mma_f16(acc[mt][j], af[mt], bf[j]);
        }
        __syncthreads();
        buf = (buf == 2) ? 0 : buf + 1;
    }

    // ---- epilogue: bias + tanh ----
    const int g = lane >> 2, tig = lane & 3;
    #pragma unroll
    for (int mt = 0; mt < 2; mt++) {
        int row0 = bm0 + wm * 32 + mt * 16 + g;
        #pragma unroll
        for (int j = 0; j < NJ; j++) {
            int col = bn0 + wn * (BN / 2) + j * 8 + tig * 2;
            float bc0 = __ldg(bias + col), bc1 = __ldg(bias + col + 1);
            float v00 = tanhf(acc[mt][j][0] + bc0);
            float v01 = tanhf(acc[mt][j][1] + bc1);
            float v10 = tanhf(acc[mt][j][2] + bc0);
            float v11 = tanhf(acc[mt][j][3] + bc1);
            if (HALF_OUT) {
                __half2 p0 = __floats2half2_rn(v00, v01);
                __half2 p1 = __floats2half2_rn(v10, v11);
                *(uint32_t*)(Ch + (size_t)row0 * N + col)       = *(uint32_t*)&p0;
                *(uint32_t*)(Ch + (size_t)(row0 + 8) * N + col) = *(uint32_t*)&p1;
            } else {
                *(float2*)(Cf + (size_t)row0 * N + col)       = make_float2(v00, v01);
                *(float2*)(Cf + (size_t)(row0 + 8) * N + col) = make_float2(v10, v11);
            }
        }
    }
}

// ---------------- final layer: sigmoid(h4 @ W5 + b5), N=1 -------------------
__global__ void k_final(const float* __restrict__ h4, const float* __restrict__ W5,
                        const float* __restrict__ b5, float* __restrict__ out) {
    int gtid = blockIdx.x * blockDim.x + threadIdx.x;
    int row = gtid >> 5;
    int lane = gtid & 31;
    if (row >= N_NODES) return;
    const float4* a = (const float4*)(h4 + (size_t)row * (HID / 4));
    const float4* w = (const float4*)W5;
    float s = 0.f;
    #pragma unroll
    for (int i = 0; i < 2; i++) {
        int v4 = lane + i * 32;
        float4 x = a[v4], y = w[v4];
        s += x.x * y.x + x.y * y.y + x.z * y.z + x.w * y.w;
    }
    #pragma unroll
    for (int o = 16; o; o >>= 1) s += __shfl_xor_sync(0xffffffffu, s, o);
    if (lane == 0) out[row] = 1.f / (1.f + expf(-(s + b5[0])));
}

// ---------------- launcher ---------------------------------------------------
extern "C" void kernel_launch(void* const* d_in, const int* in_sizes, int n_in,
                              void* d_out, int out_size) {
    const float* H  = (const float*)d_in[0];
    const float* Ro = (const float*)d_in[1];
    const float* Ri = (const float*)d_in[2];
    const float* e  = (const float*)d_in[3];
    const float* W1 = (const float*)d_in[4];   const float* b1 = (const float*)d_in[5];
    const float* W2 = (const float*)d_in[6];   const float* b2 = (const float*)d_in[7];
    const float* W3 = (const float*)d_in[8];   const float* b3 = (const float*)d_in[9];
    const float* W4 = (const float*)d_in[10];  const float* b4 = (const float*)d_in[11];
    const float* W5 = (const float*)d_in[12];  const float* b5 = (const float*)d_in[13];
    float* out = (float*)d_out;
    (void)in_sizes; (void)n_in; (void)out_size;

    __half *xp, *h1p, *h2p, *h3p, *w1, *w2, *w3, *w4;
    float* p_h4;
    cudaGetSymbolAddress((void**)&xp,  g_x);
    cudaGetSymbolAddress((void**)&h1p, g_h1);
    cudaGetSymbolAddress((void**)&h2p, g_h2);
    cudaGetSymbolAddress((void**)&h3p, g_h3);
    cudaGetSymbolAddress((void**)&p_h4, g_h4);
    cudaGetSymbolAddress((void**)&w1, g_W1);
    cudaGetSymbolAddress((void**)&w2, g_W2);
    cudaGetSymbolAddress((void**)&w3, g_W3);
    cudaGetSymbolAddress((void**)&w4, g_W4);

    const int SMEM128 = 3 * (TILE_A + 128 * 128);   // 96 KB
    const int SMEM64  = 3 * (TILE_A + 64 * 128);    // 72 KB
    cudaFuncSetAttribute(k_gemm<128, true>,  cudaFuncAttributeMaxDynamicSharedMemorySize, SMEM128);
    cudaFuncSetAttribute(k_gemm<64,  true>,  cudaFuncAttributeMaxDynamicSharedMemorySize, SMEM64);
    cudaFuncSetAttribute(k_gemm<64,  false>, cudaFuncAttributeMaxDynamicSharedMemorySize, SMEM64);

    // front-end
    k_prep<<<(N_NODES * D_IN / 4 + 255) / 256, 256>>>(H, e);
    k_wconv_all<<<2048, dim3(32, 8)>>>(W1, W2, W3, W4, w1, w2, w3, w4);
    k_extract<<<dim3(N_EDGES, 2), 128>>>(Ro, Ri);
    k_scatter<<<(N_EDGES * 32 + 255) / 256, 256>>>();
    k_concat<<<(N_NODES * 96 + 255) / 256, 256>>>(H);
    // MLP (pure fp16 MMA, fp32 accumulate, cp.async pipelined, 2 CTA/SM)
    k_gemm<128, true><<<dim3(HID / 128, N_NODES / 128), 256, SMEM128>>>(xp,  w1, b1, h1p, nullptr, HID,     3 * D_IN);
    k_gemm<128, true><<<dim3(HID / 128, N_NODES / 128), 256, SMEM128>>>(h1p, w2, b2, h2p, nullptr, HID,     HID);
    k_gemm<64,  true><<<dim3(HID / 2 / 64, N_NODES / 128), 256, SMEM64>>>(h2p, w3, b3, h3p, nullptr, HID / 2, HID);
    k_gemm<64, false><<<dim3(HID / 4 / 64, N_NODES / 128), 256, SMEM64>>>(h3p, w4, b4, nullptr, p_h4, HID / 4, HID / 2);
    // head
    k_final<<<(N_NODES * 32 + 255) / 256, 256>>>(p_h4, W5, b5, out);
}

// round 11
// speedup vs baseline: 4.4163x; 1.0427x over previous
#include <cuda_runtime.h>
#include <cuda_fp16.h>
#include <math.h>
#include <stdint.h>

#define N_NODES 4096
#define N_EDGES 16384
#define D_IN    128
#define HID     1024

// ---------------- scratch (device globals; no allocation allowed) ----------
__device__ float g_eH[N_NODES * D_IN];
__device__ float g_Ho[N_NODES * D_IN];
__device__ float g_Hi[N_NODES * D_IN];
__device__ int   g_src[N_EDGES];
__device__ int   g_dst[N_EDGES];
__device__ float g_h4[N_NODES * (HID / 4)];
// activations as single fp16 (round-to-nearest)
__device__ __half g_x [N_NODES * 3 * D_IN];
__device__ __half g_h1[N_NODES * HID];
__device__ __half g_h2[N_NODES * HID];
__device__ __half g_h3[N_NODES * (HID / 2)];
// transposed fp16 weights: [N,K] row-major
__device__ __half g_W1[HID * 3 * D_IN];
__device__ __half g_W2[HID * HID];
__device__ __half g_W3[(HID/2) * HID];
__device__ __half g_W4[(HID/4) * (HID/2)];

__device__ __forceinline__ float tanh_fast(float x) {
    float r;
    asm("tanh.approx.f32 %0, %1;" : "=f"(r) : "f"(x));
    return r;
}

// ---------------- kernel 1: eH = e*H, zero Ho/Hi ---------------------------
__global__ void k_prep(const float* __restrict__ H, const float* __restrict__ e) {
    int idx = blockIdx.x * blockDim.x + threadIdx.x;
    const int total4 = N_NODES * D_IN / 4;
    if (idx >= total4) return;
    int node = idx / (D_IN / 4);
    float ev = e[node];
    float4 h = ((const float4*)H)[idx];
    ((float4*)g_eH)[idx] = make_float4(ev * h.x, ev * h.y, ev * h.z, ev * h.w);
    float4 z = make_float4(0.f, 0.f, 0.f, 0.f);
    ((float4*)g_Ho)[idx] = z;
    ((float4*)g_Hi)[idx] = z;
}

// ---------------- kernel 2: one-hot -> index, with early exit ---------------
__global__ void k_extract(const float* __restrict__ Ro, const float* __restrict__ Ri) {
    __shared__ int found;
    int e = blockIdx.x;
    const float* row = (blockIdx.y == 0 ? Ro : Ri) + (size_t)e * N_NODES;
    int* out = (blockIdx.y == 0 ? g_src : g_dst);
    if (threadIdx.x == 0) found = 0;
    __syncthreads();
    int t = threadIdx.x;
    #pragma unroll 1
    for (int i = 0; i < 8; i++) {
        int v4 = t + i * 128;
        float4 v = ((const float4*)row)[v4];
        if (v.x != 0.f || v.y != 0.f || v.z != 0.f || v.w != 0.f) {
            int base = v4 * 4;
            int col = (v.x != 0.f) ? base : (v.y != 0.f) ? base + 1
                    : (v.z != 0.f) ? base + 2 : base + 3;
            out[e] = col;
            found = 1;
        }
        __syncthreads();
        if (found) return;
    }
}

// ---------------- kernel 3: edge scatter (vector reductions) -----------------
#define REDV4(ptr, v) \
    asm volatile("red.global.add.v4.f32 [%0], {%1,%2,%3,%4};" \
                 :: "l"(ptr), "f"((v).x), "f"((v).y), "f"((v).z), "f"((v).w) : "memory")

__global__ void k_scatter() {
    int gtid = blockIdx.x * blockDim.x + threadIdx.x;
    int warp = gtid >> 5;
    int lane = gtid & 31;
    if (warp >= N_EDGES) return;
    int s = g_src[warp];
    int d = g_dst[warp];
    float4 vs = ((const float4*)(g_eH + (size_t)s * D_IN))[lane];
    float4 vd = ((const float4*)(g_eH + (size_t)d * D_IN))[lane];
    float* ho = g_Ho + (size_t)d * D_IN + lane * 4;  // Ho[dst] += eH[src]
    float* hi = g_Hi + (size_t)s * D_IN + lane * 4;  // Hi[src] += eH[dst]
    REDV4(ho, vs);
    REDV4(hi, vd);
}

// ---------------- kernel 4: x = concat(Ho, H, Hi) -> fp16 --------------------
__global__ void k_concat(const float* __restrict__ H) {
    int idx = blockIdx.x * blockDim.x + threadIdx.x;
    const int per_row4 = 3 * D_IN / 4;
    const int total4 = N_NODES * per_row4;
    if (idx >= total4) return;
    int node = idx / per_row4;
    int c4 = idx - node * per_row4;
    float4 v;
    if (c4 < 32)       v = ((const float4*)(g_Ho + (size_t)node * D_IN))[c4];
    else if (c4 < 64)  v = ((const float4*)(H    + (size_t)node * D_IN))[c4 - 32];
    else               v = ((const float4*)(g_Hi + (size_t)node * D_IN))[c4 - 64];
    __half2 p01 = __floats2half2_rn(v.x, v.y);
    __half2 p23 = __floats2half2_rn(v.z, v.w);
    size_t off = (size_t)node * (3 * D_IN) + c4 * 4;
    *(uint2*)(g_x + off) = make_uint2(*(uint32_t*)&p01, *(uint32_t*)&p23);
}

// ---------------- fused weight transpose + fp16 convert ----------------------
__device__ __forceinline__ void wconv_tile(const float* __restrict__ W,
                                           __half* __restrict__ O,
                                           int K, int N, int bx, int by,
                                           int x, int y, float t[32][33]) {
    #pragma unroll
    for (int j = 0; j < 32; j += 8)
        t[y + j][x] = W[(size_t)(by + y + j) * N + bx + x];
    __syncthreads();
    #pragma unroll
    for (int j = 0; j < 32; j += 8) {
        int n = bx + y + j, k = by + x;
        O[(size_t)n * K + k] = __float2half_rn(t[x][y + j]);
    }
}

__global__ void k_wconv_all(const float* __restrict__ W1, const float* __restrict__ W2,
                            const float* __restrict__ W3, const float* __restrict__ W4,
                            __half* w1, __half* w2, __half* w3, __half* w4) {
    __shared__ float t[32][33];
    int b = blockIdx.x;
    int x = threadIdx.x, y = threadIdx.y;
    if (b < 384) {
        wconv_tile(W1, w1, 3 * D_IN, HID, (b % 32) * 32, (b / 32) * 32, x, y, t);
    } else if (b < 1408) {
        b -= 384;
        wconv_tile(W2, w2, HID, HID, (b % 32) * 32, (b / 32) * 32, x, y, t);
    } else if (b < 1920) {
        b -= 1408;
        wconv_tile(W3, w3, HID, HID / 2, (b % 16) * 32, (b / 16) * 32, x, y, t);
    } else {
        b -= 1920;
        wconv_tile(W4, w4, HID / 2, HID / 4, (b % 8) * 32, (b / 8) * 32, x, y, t);
    }
}

// ---------------- pipelined mma.sync GEMM (pure fp16, templated BN) ----------
// A [M,K] fp16; B [N,K] fp16. CTA 128xBN, K-chunk 64, 3-stage cp.async
// pipeline, single barrier per chunk, XOR-swizzled 128B rows, fp32 acc.
#define TILE_A 16384

__device__ __forceinline__ uint32_t smem_u32(const void* p) {
    uint32_t a;
    asm("{ .reg .u64 t; cvta.to.shared.u64 t, %1; cvt.u32.u64 %0, t; }" : "=r"(a) : "l"(p));
    return a;
}
#define SWZ(row, kg) (((row) << 7) + ((((kg) ^ ((row) & 7))) << 4))
#define CP_ASYNC16(dst, src) \
    asm volatile("cp.async.cg.shared.global [%0], [%1], 16;" :: "r"(dst), "l"(src))
#define CP_COMMIT() asm volatile("cp.async.commit_group;" ::: "memory")
#define CP_WAIT1()  asm volatile("cp.async.wait_group 1;" ::: "memory")
#define LDSM_X4(r0, r1, r2, r3, addr) \
    asm volatile("ldmatrix.sync.aligned.m8n8.x4.shared.b16 {%0,%1,%2,%3}, [%4];" \
                 : "=r"(r0), "=r"(r1), "=r"(r2), "=r"(r3) : "r"(addr))

__device__ __forceinline__ void mma_f16(float* c, const uint32_t* a, const uint32_t* b) {
    asm volatile(
        "mma.sync.aligned.m16n8k16.row.col.f32.f16.f16.f32 "
        "{%0,%1,%2,%3}, {%4,%5,%6,%7}, {%8,%9}, {%0,%1,%2,%3};"
        : "+f"(c[0]), "+f"(c[1]), "+f"(c[2]), "+f"(c[3])
        : "r"(a[0]), "r"(a[1]), "r"(a[2]), "r"(a[3]), "r"(b[0]), "r"(b[1]));
}

template <int BN, bool HALF_OUT>
__global__ void __launch_bounds__(256, 2)
k_gemm(const __half* __restrict__ A, const __half* __restrict__ B,
       const float* __restrict__ bias,
       __half* __restrict__ Ch, float* __restrict__ Cf, int N, int K) {
    constexpr int TILE_BB = BN * 128;
    constexpr int STAGE_B = TILE_A + TILE_BB;
    constexpr int OFF_B = TILE_A;
    constexpr int NJ = BN / 16;
    constexpr int B_ITERS = BN / 32;

    extern __shared__ char smem[];
    const uint32_t sb = smem_u32(smem);
    const int tid = threadIdx.x;
    const int wid = tid >> 5;
    const int lane = tid & 31;
    const int wm = wid & 3;
    const int wn = wid >> 2;
    const int bm0 = blockIdx.y * 128;
    const int bn0 = blockIdx.x * BN;
    const int nch = K >> 6;

    float acc[2][NJ][4];
    #pragma unroll
    for (int mt = 0; mt < 2; mt++)
        #pragma unroll
        for (int j = 0; j < NJ; j++)
            #pragma unroll
            for (int q = 0; q < 4; q++) acc[mt][j][q] = 0.f;

    auto issue = [&](int c, int buf) {
        uint32_t base = sb + buf * STAGE_B;
        int k0 = c << 6;
        #pragma unroll
        for (int i = 0; i < 4; i++) {
            int idx = tid + i * 256;
            int row = idx >> 3, kg = idx & 7;
            CP_ASYNC16(base + SWZ(row, kg), A + (size_t)(bm0 + row) * K + k0 + kg * 8);
        }
        #pragma unroll
        for (int i = 0; i < B_ITERS; i++) {
            int idx = tid + i * 256;
            int row = idx >> 3, kg = idx & 7;
            CP_ASYNC16(base + OFF_B + SWZ(row, kg), B + (size_t)(bn0 + row) * K + k0 + kg * 8);
        }
    };

    issue(0, 0); CP_COMMIT();
    issue(1, 1); CP_COMMIT();

    const int a_row = wm * 32 + (lane & 15);
    const int a_kg  = lane >> 4;
    const int b_row = wn * (BN / 2) + (lane & 7) + (lane >> 4) * 8;
    const int b_kg  = (lane >> 3) & 1;

    int buf = 0;
    for (int i = 0; i < nch; i++) {
        int c = i + 2;
        CP_WAIT1();           // stage i resident (commits so far = i+2)
        __syncthreads();      // all warps done reading stage (i-1)%3
        if (c < nch) issue(c, c % 3);
        CP_COMMIT();          // keep one commit per iteration (empty ok)

        uint32_t sbase = sb + buf * STAGE_B;
        #pragma unroll
        for (int ks8 = 0; ks8 < 8; ks8 += 2) {
            uint32_t af[2][4], bf[NJ][2];
            #pragma unroll
            for (int mt = 0; mt < 2; mt++) {
                uint32_t ad = sbase + SWZ(a_row + mt * 16, a_kg + ks8);
                LDSM_X4(af[mt][0], af[mt][1], af[mt][2], af[mt][3], ad);
            }
            #pragma unroll
            for (int jp = 0; jp < NJ / 2; jp++) {
                uint32_t bd = sbase + OFF_B + SWZ(b_row + jp * 16, b_kg + ks8);
                LDSM_X4(bf[jp*2][0], bf[jp*2][1], bf[jp*2+1][0], bf[jp*2+1][1], bd);
            }
            #pragma unroll
            for (int mt = 0; mt < 2; mt++)
                #pragma unroll
                for (int j = 0; j < NJ; j++)
                    mma_f16(acc[mt][j], af[mt], bf[j]);
        }
        buf = (buf == 2) ? 0 : buf + 1;
    }

    // ---- epilogue: bias + tanh ----
    const int g = lane >> 2, tig = lane & 3;
    #pragma unroll
    for (int mt = 0; mt < 2; mt++) {
        int row0 = bm0 + wm * 32 + mt * 16 + g;
        #pragma unroll
        for (int j = 0; j < NJ; j++) {
            int col = bn0 + wn * (BN / 2) + j * 8 + tig * 2;
            float bc0 = __ldg(bias + col), bc1 = __ldg(bias + col + 1);
            float v00 = tanh_fast(acc[mt][j][0] + bc0);
            float v01 = tanh_fast(acc[mt][j][1] + bc1);
            float v10 = tanh_fast(acc[mt][j][2] + bc0);
            float v11 = tanh_fast(acc[mt][j][3] + bc1);
            if (HALF_OUT) {
                __half2 p0 = __floats2half2_rn(v00, v01);
                __half2 p1 = __floats2half2_rn(v10, v11);
                *(uint32_t*)(Ch + (size_t)row0 * N + col)       = *(uint32_t*)&p0;
                *(uint32_t*)(Ch + (size_t)(row0 + 8) * N + col) = *(uint32_t*)&p1;
            } else {
                *(float2*)(Cf + (size_t)row0 * N + col)       = make_float2(v00, v01);
                *(float2*)(Cf + (size_t)(row0 + 8) * N + col) = make_float2(v10, v11);
            }
        }
    }
}

// ---------------- final layer: sigmoid(h4 @ W5 + b5), N=1 -------------------
__global__ void k_final(const float* __restrict__ h4, const float* __restrict__ W5,
                        const float* __restrict__ b5, float* __restrict__ out) {
    int gtid = blockIdx.x * blockDim.x + threadIdx.x;
    int row = gtid >> 5;
    int lane = gtid & 31;
    if (row >= N_NODES) return;
    const float4* a = (const float4*)(h4 + (size_t)row * (HID / 4));
    const float4* w = (const float4*)W5;
    float s = 0.f;
    #pragma unroll
    for (int i = 0; i < 2; i++) {
        int v4 = lane + i * 32;
        float4 x = a[v4], y = w[v4];
        s += x.x * y.x + x.y * y.y + x.z * y.z + x.w * y.w;
    }
    #pragma unroll
    for (int o = 16; o; o >>= 1) s += __shfl_xor_sync(0xffffffffu, s, o);
    if (lane == 0) out[row] = 1.f / (1.f + expf(-(s + b5[0])));
}

// ---------------- launcher ---------------------------------------------------
extern "C" void kernel_launch(void* const* d_in, const int* in_sizes, int n_in,
                              void* d_out, int out_size) {
    const float* H  = (const float*)d_in[0];
    const float* Ro = (const float*)d_in[1];
    const float* Ri = (const float*)d_in[2];
    const float* e  = (const float*)d_in[3];
    const float* W1 = (const float*)d_in[4];   const float* b1 = (const float*)d_in[5];
    const float* W2 = (const float*)d_in[6];   const float* b2 = (const float*)d_in[7];
    const float* W3 = (const float*)d_in[8];   const float* b3 = (const float*)d_in[9];
    const float* W4 = (const float*)d_in[10];  const float* b4 = (const float*)d_in[11];
    const float* W5 = (const float*)d_in[12];  const float* b5 = (const float*)d_in[13];
    float* out = (float*)d_out;
    (void)in_sizes; (void)n_in; (void)out_size;

    __half *xp, *h1p, *h2p, *h3p, *w1, *w2, *w3, *w4;
    float* p_h4;
    cudaGetSymbolAddress((void**)&xp,  g_x);
    cudaGetSymbolAddress((void**)&h1p, g_h1);
    cudaGetSymbolAddress((void**)&h2p, g_h2);
    cudaGetSymbolAddress((void**)&h3p, g_h3);
    cudaGetSymbolAddress((void**)&p_h4, g_h4);
    cudaGetSymbolAddress((void**)&w1, g_W1);
    cudaGetSymbolAddress((void**)&w2, g_W2);
    cudaGetSymbolAddress((void**)&w3, g_W3);
    cudaGetSymbolAddress((void**)&w4, g_W4);

    const int SMEM128 = 3 * (TILE_A + 128 * 128);   // 96 KB
    const int SMEM64  = 3 * (TILE_A + 64 * 128);    // 72 KB
    cudaFuncSetAttribute(k_gemm<128, true>,  cudaFuncAttributeMaxDynamicSharedMemorySize, SMEM128);
    cudaFuncSetAttribute(k_gemm<64,  true>,  cudaFuncAttributeMaxDynamicSharedMemorySize, SMEM64);
    cudaFuncSetAttribute(k_gemm<64,  false>, cudaFuncAttributeMaxDynamicSharedMemorySize, SMEM64);

    // side streams + events for graph parallelism (created once, reused)
    static cudaStream_t s_w = nullptr, s_p = nullptr;
    static cudaEvent_t ev_fork = nullptr, ev_w = nullptr, ev_p = nullptr;
    if (!s_w) {
        cudaStreamCreateWithFlags(&s_w, cudaStreamNonBlocking);
        cudaStreamCreateWithFlags(&s_p, cudaStreamNonBlocking);
        cudaEventCreateWithFlags(&ev_fork, cudaEventDisableTiming);
        cudaEventCreateWithFlags(&ev_w,    cudaEventDisableTiming);
        cudaEventCreateWithFlags(&ev_p,    cudaEventDisableTiming);
    }

    // fork: weight convert + prep run concurrently with the one-hot scan
    cudaEventRecord(ev_fork, 0);
    cudaStreamWaitEvent(s_w, ev_fork, 0);
    cudaStreamWaitEvent(s_p, ev_fork, 0);
    k_wconv_all<<<2048, dim3(32, 8), 0, s_w>>>(W1, W2, W3, W4, w1, w2, w3, w4);
    cudaEventRecord(ev_w, s_w);
    k_prep<<<(N_NODES * D_IN / 4 + 255) / 256, 256, 0, s_p>>>(H, e);
    cudaEventRecord(ev_p, s_p);

    // main chain: scan -> scatter -> concat
    k_extract<<<dim3(N_EDGES, 2), 128>>>(Ro, Ri);
    cudaStreamWaitEvent(0, ev_p, 0);          // scatter needs eH/Ho/Hi
    k_scatter<<<(N_EDGES * 32 + 255) / 256, 256>>>();
    k_concat<<<(N_NODES * 96 + 255) / 256, 256>>>(H);
    cudaStreamWaitEvent(0, ev_w, 0);          // GEMMs need converted weights

    // MLP (pure fp16 MMA, fp32 accumulate, cp.async pipelined, 2 CTA/SM)
    k_gemm<128, true><<<dim3(HID / 128, N_NODES / 128), 256, SMEM128>>>(xp,  w1, b1, h1p, nullptr, HID,     3 * D_IN);
    k_gemm<128, true><<<dim3(HID / 128, N_NODES / 128), 256, SMEM128>>>(h1p, w2, b2, h2p, nullptr, HID,     HID);
    k_gemm<64,  true><<<dim3(HID / 2 / 64, N_NODES / 128), 256, SMEM64>>>(h2p, w3, b3, h3p, nullptr, HID / 2, HID);
    k_gemm<64, false><<<dim3(HID / 4 / 64, N_NODES / 128), 256, SMEM64>>>(h3p, w4, b4, nullptr, p_h4, HID / 4, HID / 2);
    // head
    k_final<<<(N_NODES * 32 + 255) / 256, 256>>>(p_h4, W5, b5, out);
}